// round 6
// baseline (speedup 1.0000x reference)
#include <cuda_runtime.h>
#include <cuda_bf16.h>
#include <math.h>
#include <stdint.h>

#define B_    32
#define TK_   2048
#define N_    1024
#define M_    (B_ * TK_)        // 65536
#define KTOT  2048
#define NPART 16                // N_/64 column blocks -> score partials

// ---------------- scratch (no allocs allowed) ----------------
__device__ float g_dec[B_ * N_];
__device__ float g_part[NPART * M_];
__device__ float g_ct[8 * B_ * N_];
// pre-converted bf16 hi/lo operands: A = [h|q] over K, B = [Wh|Wq] over K
__device__ __nv_bfloat16 g_Ahi[(size_t)M_ * KTOT];
__device__ __nv_bfloat16 g_Alo[(size_t)M_ * KTOT];
__device__ __nv_bfloat16 g_Bhi[(size_t)N_ * KTOT];
__device__ __nv_bfloat16 g_Blo[(size_t)N_ * KTOT];

// ---------------- smem layout (dynamic) ----------------
// bf16 tiles, row stride 40 elements (80B): conflict-free ldmatrix
#define A_HI 0
#define A_LO 10240
#define B_HI 20480
#define B_LO 25600
#define STAGE_BYTES 30720
#define NSTAGE 3
#define EPI_DEC (NSTAGE * STAGE_BYTES)     // 92160
#define EPI_WC  (EPI_DEC + 256)
#define EPI_VW  (EPI_WC + 256)
#define EPI_COV (EPI_VW + 256)
#define EPI_RED (EPI_COV + 512)            // 128*8 floats = 4096B
#define SMEM_TOTAL (EPI_RED + 4096)        // 97536

__device__ __forceinline__ uint32_t smem_u32(const void* p) {
    uint32_t a;
    asm("{ .reg .u64 t; cvta.to.shared.u64 t, %1; cvt.u32.u64 %0, t; }" : "=r"(a) : "l"(p));
    return a;
}

#define LDSM_X4(r0, r1, r2, r3, addr) \
    asm volatile("ldmatrix.sync.aligned.m8n8.x4.shared.b16 {%0,%1,%2,%3}, [%4];" \
                 : "=r"(r0), "=r"(r1), "=r"(r2), "=r"(r3) : "r"(addr))
#define MMA16816(d, a, b) \
    asm volatile("mma.sync.aligned.m16n8k16.row.col.f32.bf16.bf16.f32 " \
                 "{%0,%1,%2,%3}, {%4,%5,%6,%7}, {%8,%9}, {%0,%1,%2,%3};" \
                 : "+f"((d)[0]), "+f"((d)[1]), "+f"((d)[2]), "+f"((d)[3]) \
                 : "r"((a)[0]), "r"((a)[1]), "r"((a)[2]), "r"((a)[3]), \
                   "r"((b)[0]), "r"((b)[1]))
#define CP16(smaddr, gptr) \
    asm volatile("cp.async.cg.shared.global [%0], [%1], 16;" \
                 :: "r"(smaddr), "l"(gptr) : "memory")
#define CP_COMMIT() asm volatile("cp.async.commit_group;" ::: "memory")
#define CP_WAIT1()  asm volatile("cp.async.wait_group 1;" ::: "memory")

// fp32x4 -> bf16 hi/lo split
__device__ __forceinline__ void split4(float4 v, uint2& hi, uint2& lo) {
    uint32_t hi01, hi23, lo01, lo23;
    asm("cvt.rn.bf16x2.f32 %0, %1, %2;" : "=r"(hi01) : "f"(v.y), "f"(v.x));
    asm("cvt.rn.bf16x2.f32 %0, %1, %2;" : "=r"(hi23) : "f"(v.w), "f"(v.z));
    float rx = v.x - __uint_as_float(hi01 << 16);
    float ry = v.y - __uint_as_float(hi01 & 0xffff0000u);
    float rz = v.z - __uint_as_float(hi23 << 16);
    float rw = v.w - __uint_as_float(hi23 & 0xffff0000u);
    asm("cvt.rn.bf16x2.f32 %0, %1, %2;" : "=r"(lo01) : "f"(ry), "f"(rx));
    asm("cvt.rn.bf16x2.f32 %0, %1, %2;" : "=r"(lo23) : "f"(rw), "f"(rz));
    hi = make_uint2(hi01, hi23);
    lo = make_uint2(lo01, lo23);
}

// ===========================================================================
// pre-conversion kernels
// ===========================================================================
__global__ __launch_bounds__(256) void conv_a_kernel(
    const float* __restrict__ h, const float* __restrict__ q)
{
    const size_t UN = (size_t)M_ * (N_ / 4);
    const size_t total = 2 * UN;
    for (size_t u = (size_t)blockIdx.x * 256 + threadIdx.x; u < total;
         u += (size_t)gridDim.x * 256) {
        const int t = (u >= UN) ? 1 : 0;
        const size_t v = u - (t ? UN : 0);
        const size_t m = v >> 8;
        const int seg = (int)(v & 255);
        float4 val = *(const float4*)((t ? q : h) + m * N_ + seg * 4);
        uint2 hi, lo;
        split4(val, hi, lo);
        size_t d = m * (size_t)KTOT + (size_t)t * N_ + (size_t)seg * 4;
        *(uint2*)(g_Ahi + d) = hi;
        *(uint2*)(g_Alo + d) = lo;
    }
}

__global__ __launch_bounds__(256) void conv_b_kernel(
    const float* __restrict__ Wh, const float* __restrict__ Wq)
{
    const size_t UN = (size_t)N_ * (N_ / 4);
    const size_t total = 2 * UN;
    for (size_t u = (size_t)blockIdx.x * 256 + threadIdx.x; u < total;
         u += (size_t)gridDim.x * 256) {
        const int t = (u >= UN) ? 1 : 0;
        const size_t v = u - (t ? UN : 0);
        const size_t n = v >> 8;
        const int seg = (int)(v & 255);
        float4 val = *(const float4*)((t ? Wq : Wh) + n * N_ + seg * 4);
        uint2 hi, lo;
        split4(val, hi, lo);
        size_t d = n * (size_t)KTOT + (size_t)t * N_ + (size_t)seg * 4;
        *(uint2*)(g_Bhi + d) = hi;
        *(uint2*)(g_Blo + d) = lo;
    }
}

// ===========================================================================
// dec_feat[b][m] = s_t_hat[b] . W_d[m] + b_d[m]
// ===========================================================================
__global__ __launch_bounds__(256) void dec_kernel(
    const float* __restrict__ s_t_hat,
    const float* __restrict__ Wd,
    const float* __restrict__ bd)
{
    int b    = blockIdx.x;
    int warp = threadIdx.x >> 5;
    int lane = threadIdx.x & 31;
    int m    = blockIdx.y * 8 + warp;

    const float* sp = s_t_hat + (size_t)b * N_;
    const float* wp = Wd + (size_t)m * N_;
    float acc = 0.f;
    #pragma unroll 4
    for (int k = lane; k < N_; k += 32) acc = fmaf(sp[k], wp[k], acc);
    #pragma unroll
    for (int o = 16; o > 0; o >>= 1) acc += __shfl_xor_sync(0xffffffffu, acc, o);
    if (lane == 0) g_dec[(size_t)b * N_ + m] = acc + bd[m];
}

// ===========================================================================
// scores via bf16 mma.sync (3-term split) on pre-converted operands.
// Block tile 128x64, 128 threads (4 warps, 2m x 2n, 64x32 per warp).
// NSTAGE=3 cp.async pipeline, 2 CTAs/SM. grid (16, 512).
// ===========================================================================
__global__ __launch_bounds__(128, 2) void scores_mma(
    const float* __restrict__ Wc, const float* __restrict__ vw,
    const float* __restrict__ cov)
{
    extern __shared__ char sm[];
    const uint32_t smem = smem_u32(sm);
    const int tid  = threadIdx.x;
    const int lane = tid & 31;
    const int wid  = tid >> 5;
    const int wm   = wid & 1;       // 2 m-groups of 64
    const int wn   = wid >> 1;      // 2 n-groups of 32
    const int mBase = blockIdx.y * 128;
    const int nBase = blockIdx.x * 64;
    const int b     = mBase >> 11;
    const int trow  = mBase & (TK_ - 1);

    float* dec_s = (float*)(sm + EPI_DEC);
    float* wc_s  = (float*)(sm + EPI_WC);
    float* vw_s  = (float*)(sm + EPI_VW);
    float* cov_s = (float*)(sm + EPI_COV);
    float* red   = (float*)(sm + EPI_RED);

    if (tid < 64) {
        dec_s[tid] = g_dec[(size_t)b * N_ + nBase + tid];
        wc_s[tid]  = Wc[nBase + tid];
        vw_s[tid]  = vw[nBase + tid];
    }
    cov_s[tid] = cov[(size_t)b * TK_ + trow + tid];

    // ldmatrix lane-address components
    const int g = lane >> 3;
    const uint32_t a_row = (uint32_t)(((g & 1) << 3) + (lane & 7));
    const uint32_t a_col = (uint32_t)((g >> 1) << 3);
    const uint32_t b4_n  = (uint32_t)((lane >> 4) << 3);        // 0 or 8
    const uint32_t b4_k  = (uint32_t)(((lane >> 3) & 1) << 3);  // 0 or 8
    const uint32_t b4_r  = (uint32_t)(lane & 7);

    // cp.async unit: u covers row u>>2, 16B-seg u&3
    const int rr = tid >> 2, ss = tid & 3;

    float acc[4][4][4];
    #pragma unroll
    for (int mf = 0; mf < 4; mf++)
        #pragma unroll
        for (int nf = 0; nf < 4; nf++)
            #pragma unroll
            for (int x = 0; x < 4; x++) acc[mf][nf][x] = 0.f;

    auto cp_stage = [&](int ks, int st) {
        const uint32_t sbase = smem + st * STAGE_BYTES;
        const int k0 = ks * 32;
        #pragma unroll
        for (int j = 0; j < 4; j++) {           // A: 4 units/thread
            const int row = rr + j * 32;
            const uint32_t soff = (uint32_t)(row * 80 + ss * 16);
            const size_t ga = (size_t)(mBase + row) * KTOT + k0 + ss * 8;
            CP16(sbase + A_HI + soff, g_Ahi + ga);
            CP16(sbase + A_LO + soff, g_Alo + ga);
        }
        #pragma unroll
        for (int j = 0; j < 2; j++) {           // B: 2 units/thread
            const int row = rr + j * 32;
            const uint32_t soff = (uint32_t)(row * 80 + ss * 16);
            const size_t gb = (size_t)(nBase + row) * KTOT + k0 + ss * 8;
            CP16(sbase + B_HI + soff, g_Bhi + gb);
            CP16(sbase + B_LO + soff, g_Blo + gb);
        }
    };

    auto mma_step = [&](int st) {
        const uint32_t Ahi = smem + st * STAGE_BYTES + A_HI;
        const uint32_t Alo = smem + st * STAGE_BYTES + A_LO;
        const uint32_t Bhi = smem + st * STAGE_BYTES + B_HI;
        const uint32_t Blo = smem + st * STAGE_BYTES + B_LO;
        #pragma unroll
        for (int kf = 0; kf < 2; kf++) {
            uint32_t ah[4][4], al[4][4], bh[4][2], bl[4][2];
            #pragma unroll
            for (int mf = 0; mf < 4; mf++) {
                uint32_t off = (uint32_t)((wm * 64 + mf * 16 + a_row) * 80 + (kf * 16 + a_col) * 2);
                LDSM_X4(ah[mf][0], ah[mf][1], ah[mf][2], ah[mf][3], Ahi + off);
                LDSM_X4(al[mf][0], al[mf][1], al[mf][2], al[mf][3], Alo + off);
            }
            #pragma unroll
            for (int np = 0; np < 2; np++) {
                uint32_t off = (uint32_t)((wn * 32 + np * 16 + b4_n + b4_r) * 80 + (kf * 16 + b4_k) * 2);
                LDSM_X4(bh[np*2][0], bh[np*2][1], bh[np*2+1][0], bh[np*2+1][1], Bhi + off);
                LDSM_X4(bl[np*2][0], bl[np*2][1], bl[np*2+1][0], bl[np*2+1][1], Blo + off);
            }
            #pragma unroll
            for (int mf = 0; mf < 4; mf++)
                #pragma unroll
                for (int nf = 0; nf < 4; nf++) {
                    MMA16816(acc[mf][nf], ah[mf], bh[nf]);
                    MMA16816(acc[mf][nf], ah[mf], bl[nf]);
                    MMA16816(acc[mf][nf], al[mf], bh[nf]);
                }
        }
    };

    // prologue: fill NSTAGE-1 = 2 stages
    cp_stage(0, 0); CP_COMMIT();
    cp_stage(1, 1); CP_COMMIT();

    const int NKS = KTOT / 32;   // 64
    int cur = 0, nxt = 2;        // stage indices mod 3
    for (int ks = 0; ks < NKS; ks++) {
        CP_WAIT1();
        __syncthreads();
        mma_step(cur);
        const int pf = ks + 2;
        if (pf < NKS) cp_stage(pf, nxt);
        CP_COMMIT();
        cur = (cur == 2) ? 0 : cur + 1;
        nxt = (nxt == 2) ? 0 : nxt + 1;
    }

    // fused epilogue: tanh + dot with v_w, per-row partials
    #pragma unroll
    for (int mf = 0; mf < 4; mf++) {
        const int rA = wm * 64 + mf * 16 + (lane >> 2);
        const int rB = rA + 8;
        const float covA = cov_s[rA];
        const float covB = cov_s[rB];
        float sA = 0.f, sB = 0.f;
        #pragma unroll
        for (int nf = 0; nf < 4; nf++) {
            const int n0 = wn * 32 + nf * 8 + ((lane & 3) << 1);
            const float d0 = dec_s[n0],   d1 = dec_s[n0 + 1];
            const float w0 = wc_s[n0],    w1 = wc_s[n0 + 1];
            const float v0 = vw_s[n0],    v1 = vw_s[n0 + 1];
            sA += tanhf(acc[mf][nf][0] + d0 + covA * w0) * v0
                + tanhf(acc[mf][nf][1] + d1 + covA * w1) * v1;
            sB += tanhf(acc[mf][nf][2] + d0 + covB * w0) * v0
                + tanhf(acc[mf][nf][3] + d1 + covB * w1) * v1;
        }
        const int colslot = wn * 4 + (lane & 3);
        red[rA * 8 + colslot] = sA;
        red[rB * 8 + colslot] = sB;
    }
    __syncthreads();
    {
        float s = 0.f;
        #pragma unroll
        for (int x = 0; x < 8; x++) s += red[tid * 8 + x];
        g_part[(size_t)blockIdx.x * M_ + mBase + tid] = s;
    }
}

// ===========================================================================
// softmax with mask + renormalize; writes attn and coverage_out
// ===========================================================================
__global__ __launch_bounds__(256) void softmax_kernel(
    const float* __restrict__ mask,
    const float* __restrict__ cov,
    float* __restrict__ out)
{
    __shared__ float sh[TK_];
    __shared__ float red[256];
    const int b = blockIdx.x, tid = threadIdx.x;

    float lmax = -1e30f;
    for (int t = tid; t < TK_; t += 256) {
        float s = 0.f;
        #pragma unroll
        for (int c = 0; c < NPART; c++) s += g_part[(size_t)c * M_ + (size_t)b * TK_ + t];
        sh[t] = s;
        lmax = fmaxf(lmax, s);
    }
    red[tid] = lmax; __syncthreads();
    for (int o = 128; o > 0; o >>= 1) {
        if (tid < o) red[tid] = fmaxf(red[tid], red[tid + o]);
        __syncthreads();
    }
    const float mx = red[0];
    __syncthreads();

    float lsum = 0.f;
    for (int t = tid; t < TK_; t += 256) {
        float e = expf(sh[t] - mx) * mask[(size_t)b * TK_ + t];
        sh[t] = e;
        lsum += e;
    }
    red[tid] = lsum; __syncthreads();
    for (int o = 128; o > 0; o >>= 1) {
        if (tid < o) red[tid] += red[tid + o];
        __syncthreads();
    }
    const float inv = 1.f / red[0];

    for (int t = tid; t < TK_; t += 256) {
        float a = sh[t] * inv;
        out[(size_t)B_ * N_ + (size_t)b * TK_ + t] = a;
        out[(size_t)B_ * N_ + (size_t)B_ * TK_ + (size_t)b * TK_ + t] =
            cov[(size_t)b * TK_ + t] + a;
    }
}

// ===========================================================================
// c_t partials over 8 T-chunks, then reduce
// ===========================================================================
__global__ __launch_bounds__(256) void ct_part_kernel(
    const float* __restrict__ h,
    const float* __restrict__ out)
{
    __shared__ float ash[256];
    const int b = blockIdx.x;
    const int n = blockIdx.y * 256 + threadIdx.x;
    const int z = blockIdx.z;
    const float* attn = out + (size_t)B_ * N_ + (size_t)b * TK_ + z * 256;

    ash[threadIdx.x] = attn[threadIdx.x];
    __syncthreads();
    const float* hp = h + ((size_t)b * TK_ + z * 256) * N_ + n;
    float acc = 0.f;
    #pragma unroll 8
    for (int tt = 0; tt < 256; tt++)
        acc = fmaf(ash[tt], hp[(size_t)tt * N_], acc);
    g_ct[((size_t)z * B_ + b) * N_ + n] = acc;
}

__global__ __launch_bounds__(256) void ct_reduce_kernel(float* __restrict__ out)
{
    const int i = blockIdx.x * 256 + threadIdx.x;
    float s = 0.f;
    #pragma unroll
    for (int z = 0; z < 8; z++) s += g_ct[(size_t)z * B_ * N_ + i];
    out[i] = s;
}

// ===========================================================================
extern "C" void kernel_launch(void* const* d_in, const int* in_sizes, int n_in,
                              void* d_out, int out_size)
{
    const float* s_t_hat = (const float*)d_in[0];
    const float* h       = (const float*)d_in[1];
    const float* mask    = (const float*)d_in[2];
    const float* cov     = (const float*)d_in[3];
    const float* q_h     = (const float*)d_in[4];
    const float* Wh      = (const float*)d_in[5];
    const float* Wq      = (const float*)d_in[6];
    const float* Wc      = (const float*)d_in[7];
    const float* Wd      = (const float*)d_in[8];
    const float* bd      = (const float*)d_in[9];
    const float* vw      = (const float*)d_in[10];
    float* out = (float*)d_out;

    static bool attr_set = false;
    if (!attr_set) {
        cudaFuncSetAttribute(scores_mma, cudaFuncAttributeMaxDynamicSharedMemorySize, SMEM_TOTAL);
        attr_set = true;
    }

    conv_a_kernel<<<16384, 256>>>(h, q_h);
    conv_b_kernel<<<2048, 256>>>(Wh, Wq);
    dec_kernel<<<dim3(32, 128), 256>>>(s_t_hat, Wd, bd);
    scores_mma<<<dim3(NPART, M_ / 128), 128, SMEM_TOTAL>>>(Wc, vw, cov);
    softmax_kernel<<<32, 256>>>(mask, cov, out);
    ct_part_kernel<<<dim3(32, N_ / 256, 8), 256>>>(h, out);
    ct_reduce_kernel<<<B_ * N_ / 256, 256>>>(out);
}

// round 9
// speedup vs baseline: 1.3246x; 1.3246x over previous
#include <cuda_runtime.h>
#include <cuda_fp16.h>
#include <math.h>
#include <stdint.h>

#define B_    32
#define TK_   2048
#define N_    1024
#define M_    (B_ * TK_)        // 65536
#define KTOT  2048
#define NPART 8                 // N_/128 column blocks -> score partials

// ---------------- scratch (no allocs allowed) ----------------
__device__ float g_dec[B_ * N_];
__device__ float g_part[NPART * M_];
__device__ float g_ct[8 * B_ * N_];
// pre-converted operands: A = [h|q] single fp16; B = [Wh|Wq] fp16 hi+lo split
__device__ __half g_A[(size_t)M_ * KTOT];
__device__ __half g_Bhi[(size_t)N_ * KTOT];
__device__ __half g_Blo[(size_t)N_ * KTOT];

// ---------------- smem layout (dynamic) ----------------
// fp16 tiles, row stride 40 elements (80B): conflict-free ldmatrix
#define A_OFF  0
#define BH_OFF 10240
#define BL_OFF 20480
#define STAGE_BYTES 30720
#define NSTAGE 4
#define EPI_DEC (NSTAGE * STAGE_BYTES)     // 122880
#define EPI_WC  (EPI_DEC + 512)
#define EPI_VW  (EPI_WC + 512)
#define EPI_COV (EPI_VW + 512)
#define EPI_RED (EPI_COV + 512)            // 128*16 floats = 8192B
#define SMEM_TOTAL (EPI_RED + 8192)        // 133120

__device__ __forceinline__ uint32_t smem_u32(const void* p) {
    uint32_t a;
    asm("{ .reg .u64 t; cvta.to.shared.u64 t, %1; cvt.u32.u64 %0, t; }" : "=r"(a) : "l"(p));
    return a;
}

// pack two fp32 into one uint32 holding fp16x2 (lo = x, hi = y)
__device__ __forceinline__ uint32_t pack_h2(float x, float y) {
    uint32_t r;
    asm("cvt.rn.f16x2.f32 %0, %1, %2;" : "=r"(r) : "f"(y), "f"(x));
    return r;
}

#define LDSM_X4(r0, r1, r2, r3, addr) \
    asm volatile("ldmatrix.sync.aligned.m8n8.x4.shared.b16 {%0,%1,%2,%3}, [%4];" \
                 : "=r"(r0), "=r"(r1), "=r"(r2), "=r"(r3) : "r"(addr))
#define MMA16816F16(d, a, b) \
    asm volatile("mma.sync.aligned.m16n8k16.row.col.f32.f16.f16.f32 " \
                 "{%0,%1,%2,%3}, {%4,%5,%6,%7}, {%8,%9}, {%0,%1,%2,%3};" \
                 : "+f"((d)[0]), "+f"((d)[1]), "+f"((d)[2]), "+f"((d)[3]) \
                 : "r"((a)[0]), "r"((a)[1]), "r"((a)[2]), "r"((a)[3]), \
                   "r"((b)[0]), "r"((b)[1]))
#define CP16(smaddr, gptr) \
    asm volatile("cp.async.cg.shared.global [%0], [%1], 16;" \
                 :: "r"(smaddr), "l"(gptr) : "memory")
#define CP_COMMIT() asm volatile("cp.async.commit_group;" ::: "memory")
#define CP_WAIT2()  asm volatile("cp.async.wait_group 2;" ::: "memory")

// ===========================================================================
// pre-conversion kernels
// ===========================================================================
// A: fp16 single-precision copy of [h|q], K-contiguous fused layout
__global__ __launch_bounds__(256) void conv_a_kernel(
    const float* __restrict__ h, const float* __restrict__ q)
{
    const size_t UN = (size_t)M_ * (N_ / 4);
    const size_t total = 2 * UN;
    for (size_t u = (size_t)blockIdx.x * 256 + threadIdx.x; u < total;
         u += (size_t)gridDim.x * 256) {
        const int t = (u >= UN) ? 1 : 0;
        const size_t v = u - (t ? UN : 0);
        const size_t m = v >> 8;
        const int seg = (int)(v & 255);
        float4 val = *(const float4*)((t ? q : h) + m * N_ + seg * 4);
        size_t d = m * (size_t)KTOT + (size_t)t * N_ + (size_t)seg * 4;
        *(uint2*)(g_A + d) = make_uint2(pack_h2(val.x, val.y), pack_h2(val.z, val.w));
    }
}

// B: fp16 hi + lo split of [Wh|Wq]
__global__ __launch_bounds__(256) void conv_b_kernel(
    const float* __restrict__ Wh, const float* __restrict__ Wq)
{
    const size_t UN = (size_t)N_ * (N_ / 4);
    const size_t total = 2 * UN;
    for (size_t u = (size_t)blockIdx.x * 256 + threadIdx.x; u < total;
         u += (size_t)gridDim.x * 256) {
        const int t = (u >= UN) ? 1 : 0;
        const size_t v = u - (t ? UN : 0);
        const size_t n = v >> 8;
        const int seg = (int)(v & 255);
        float4 val = *(const float4*)((t ? Wq : Wh) + n * N_ + seg * 4);
        float hx = __half2float(__float2half_rn(val.x));
        float hy = __half2float(__float2half_rn(val.y));
        float hz = __half2float(__float2half_rn(val.z));
        float hw = __half2float(__float2half_rn(val.w));
        size_t d = n * (size_t)KTOT + (size_t)t * N_ + (size_t)seg * 4;
        *(uint2*)(g_Bhi + d) = make_uint2(pack_h2(hx, hy), pack_h2(hz, hw));
        *(uint2*)(g_Blo + d) = make_uint2(pack_h2(val.x - hx, val.y - hy),
                                          pack_h2(val.z - hz, val.w - hw));
    }
}

// ===========================================================================
// dec_feat[b][m] = s_t_hat[b] . W_d[m] + b_d[m]
// ===========================================================================
__global__ __launch_bounds__(256) void dec_kernel(
    const float* __restrict__ s_t_hat,
    const float* __restrict__ Wd,
    const float* __restrict__ bd)
{
    int b    = blockIdx.x;
    int warp = threadIdx.x >> 5;
    int lane = threadIdx.x & 31;
    int m    = blockIdx.y * 8 + warp;

    const float* sp = s_t_hat + (size_t)b * N_;
    const float* wp = Wd + (size_t)m * N_;
    float acc = 0.f;
    #pragma unroll 4
    for (int k = lane; k < N_; k += 32) acc = fmaf(sp[k], wp[k], acc);
    #pragma unroll
    for (int o = 16; o > 0; o >>= 1) acc += __shfl_xor_sync(0xffffffffu, acc, o);
    if (lane == 0) g_dec[(size_t)b * N_ + m] = acc + bd[m];
}

// ===========================================================================
// scores via fp16 mma.sync, 2-term split (a*bh + a*bl).
// Block tile 128x128, 256 threads (8 warps, 2m x 4n, 64x32 per warp).
// NSTAGE=4 cp.async pipeline. grid (8, 512).
// ===========================================================================
__global__ __launch_bounds__(256, 1) void scores_mma(
    const float* __restrict__ Wc, const float* __restrict__ vw,
    const float* __restrict__ cov)
{
    extern __shared__ char sm[];
    const uint32_t smem = smem_u32(sm);
    const int tid  = threadIdx.x;
    const int lane = tid & 31;
    const int wid  = tid >> 5;
    const int wm   = wid & 1;       // 2 m-groups of 64
    const int wn   = wid >> 1;      // 4 n-groups of 32
    const int mBase = blockIdx.y * 128;
    const int nBase = blockIdx.x * 128;
    const int b     = mBase >> 11;
    const int trow  = mBase & (TK_ - 1);

    float* dec_s = (float*)(sm + EPI_DEC);
    float* wc_s  = (float*)(sm + EPI_WC);
    float* vw_s  = (float*)(sm + EPI_VW);
    float* cov_s = (float*)(sm + EPI_COV);
    float* red   = (float*)(sm + EPI_RED);

    if (tid < 128) {
        dec_s[tid] = g_dec[(size_t)b * N_ + nBase + tid];
        wc_s[tid]  = Wc[nBase + tid];
        vw_s[tid]  = vw[nBase + tid];
        cov_s[tid] = cov[(size_t)b * TK_ + trow + tid];
    }

    // ldmatrix lane-address components
    const int g = lane >> 3;
    const uint32_t a_row = (uint32_t)(((g & 1) << 3) + (lane & 7));
    const uint32_t a_col = (uint32_t)((g >> 1) << 3);
    const uint32_t b4_n  = (uint32_t)((lane >> 4) << 3);        // 0 or 8
    const uint32_t b4_k  = (uint32_t)(((lane >> 3) & 1) << 3);  // 0 or 8
    const uint32_t b4_r  = (uint32_t)(lane & 7);

    // cp.async unit: u covers row u>>2 (0..63), 16B-seg u&3
    const int rr = tid >> 2, ss = tid & 3;

    float acc[4][4][4];
    #pragma unroll
    for (int mf = 0; mf < 4; mf++)
        #pragma unroll
        for (int nf = 0; nf < 4; nf++)
            #pragma unroll
            for (int x = 0; x < 4; x++) acc[mf][nf][x] = 0.f;

    auto cp_stage = [&](int ks, int st) {
        const uint32_t sbase = smem + st * STAGE_BYTES;
        const int k0 = ks * 32;
        #pragma unroll
        for (int j = 0; j < 2; j++) {
            const int row = rr + j * 64;
            const uint32_t soff = (uint32_t)(row * 80 + ss * 16);
            const size_t ga = (size_t)(mBase + row) * KTOT + k0 + ss * 8;
            const size_t gb = (size_t)(nBase + row) * KTOT + k0 + ss * 8;
            CP16(sbase + A_OFF + soff, g_A + ga);
            CP16(sbase + BH_OFF + soff, g_Bhi + gb);
            CP16(sbase + BL_OFF + soff, g_Blo + gb);
        }
    };

    auto mma_step = [&](int st) {
        const uint32_t Ab  = smem + st * STAGE_BYTES + A_OFF;
        const uint32_t Bh  = smem + st * STAGE_BYTES + BH_OFF;
        const uint32_t Bl  = smem + st * STAGE_BYTES + BL_OFF;
        #pragma unroll
        for (int kf = 0; kf < 2; kf++) {
            uint32_t ah[4][4], bh[4][2], bl[4][2];
            #pragma unroll
            for (int mf = 0; mf < 4; mf++) {
                uint32_t off = (uint32_t)((wm * 64 + mf * 16 + a_row) * 80 + (kf * 16 + a_col) * 2);
                LDSM_X4(ah[mf][0], ah[mf][1], ah[mf][2], ah[mf][3], Ab + off);
            }
            #pragma unroll
            for (int np = 0; np < 2; np++) {
                uint32_t off = (uint32_t)((wn * 32 + np * 16 + b4_n + b4_r) * 80 + (kf * 16 + b4_k) * 2);
                LDSM_X4(bh[np*2][0], bh[np*2][1], bh[np*2+1][0], bh[np*2+1][1], Bh + off);
                LDSM_X4(bl[np*2][0], bl[np*2][1], bl[np*2+1][0], bl[np*2+1][1], Bl + off);
            }
            #pragma unroll
            for (int mf = 0; mf < 4; mf++)
                #pragma unroll
                for (int nf = 0; nf < 4; nf++) {
                    MMA16816F16(acc[mf][nf], ah[mf], bh[nf]);
                    MMA16816F16(acc[mf][nf], ah[mf], bl[nf]);
                }
        }
    };

    // prologue: fill NSTAGE-1 = 3 stages
    cp_stage(0, 0); CP_COMMIT();
    cp_stage(1, 1); CP_COMMIT();
    cp_stage(2, 2); CP_COMMIT();

    const int NKS = KTOT / 32;   // 64
    for (int ks = 0; ks < NKS; ks++) {
        CP_WAIT2();
        __syncthreads();
        const int pf = ks + NSTAGE - 1;
        if (pf < NKS) cp_stage(pf, pf & (NSTAGE - 1));
        CP_COMMIT();
        mma_step(ks & (NSTAGE - 1));
    }

    // fused epilogue: tanh + dot with v_w, per-row partials
    #pragma unroll
    for (int mf = 0; mf < 4; mf++) {
        const int rA = wm * 64 + mf * 16 + (lane >> 2);
        const int rB = rA + 8;
        const float covA = cov_s[rA];
        const float covB = cov_s[rB];
        float sA = 0.f, sB = 0.f;
        #pragma unroll
        for (int nf = 0; nf < 4; nf++) {
            const int n0 = wn * 32 + nf * 8 + ((lane & 3) << 1);
            const float d0 = dec_s[n0],   d1 = dec_s[n0 + 1];
            const float w0 = wc_s[n0],    w1 = wc_s[n0 + 1];
            const float v0 = vw_s[n0],    v1 = vw_s[n0 + 1];
            sA += tanhf(acc[mf][nf][0] + d0 + covA * w0) * v0
                + tanhf(acc[mf][nf][1] + d1 + covA * w1) * v1;
            sB += tanhf(acc[mf][nf][2] + d0 + covB * w0) * v0
                + tanhf(acc[mf][nf][3] + d1 + covB * w1) * v1;
        }
        const int colslot = wn * 4 + (lane & 3);
        red[rA * 16 + colslot] = sA;
        red[rB * 16 + colslot] = sB;
    }
    __syncthreads();
    if (tid < 128) {
        float s = 0.f;
        #pragma unroll
        for (int x = 0; x < 16; x++) s += red[tid * 16 + x];
        g_part[(size_t)blockIdx.x * M_ + mBase + tid] = s;
    }
}

// ===========================================================================
// softmax with mask + renormalize; writes attn and coverage_out
// ===========================================================================
__global__ __launch_bounds__(256) void softmax_kernel(
    const float* __restrict__ mask,
    const float* __restrict__ cov,
    float* __restrict__ out)
{
    __shared__ float sh[TK_];
    __shared__ float red[256];
    const int b = blockIdx.x, tid = threadIdx.x;

    float lmax = -1e30f;
    for (int t = tid; t < TK_; t += 256) {
        float s = 0.f;
        #pragma unroll
        for (int c = 0; c < NPART; c++) s += g_part[(size_t)c * M_ + (size_t)b * TK_ + t];
        sh[t] = s;
        lmax = fmaxf(lmax, s);
    }
    red[tid] = lmax; __syncthreads();
    for (int o = 128; o > 0; o >>= 1) {
        if (tid < o) red[tid] = fmaxf(red[tid], red[tid + o]);
        __syncthreads();
    }
    const float mx = red[0];
    __syncthreads();

    float lsum = 0.f;
    for (int t = tid; t < TK_; t += 256) {
        float e = expf(sh[t] - mx) * mask[(size_t)b * TK_ + t];
        sh[t] = e;
        lsum += e;
    }
    red[tid] = lsum; __syncthreads();
    for (int o = 128; o > 0; o >>= 1) {
        if (tid < o) red[tid] += red[tid + o];
        __syncthreads();
    }
    const float inv = 1.f / red[0];

    for (int t = tid; t < TK_; t += 256) {
        float a = sh[t] * inv;
        out[(size_t)B_ * N_ + (size_t)b * TK_ + t] = a;
        out[(size_t)B_ * N_ + (size_t)B_ * TK_ + (size_t)b * TK_ + t] =
            cov[(size_t)b * TK_ + t] + a;
    }
}

// ===========================================================================
// c_t partials over 8 T-chunks, then reduce
// ===========================================================================
__global__ __launch_bounds__(256) void ct_part_kernel(
    const float* __restrict__ h,
    const float* __restrict__ out)
{
    __shared__ float ash[256];
    const int b = blockIdx.x;
    const int n = blockIdx.y * 256 + threadIdx.x;
    const int z = blockIdx.z;
    const float* attn = out + (size_t)B_ * N_ + (size_t)b * TK_ + z * 256;

    ash[threadIdx.x] = attn[threadIdx.x];
    __syncthreads();
    const float* hp = h + ((size_t)b * TK_ + z * 256) * N_ + n;
    float acc = 0.f;
    #pragma unroll 8
    for (int tt = 0; tt < 256; tt++)
        acc = fmaf(ash[tt], hp[(size_t)tt * N_], acc);
    g_ct[((size_t)z * B_ + b) * N_ + n] = acc;
}

__global__ __launch_bounds__(256) void ct_reduce_kernel(float* __restrict__ out)
{
    const int i = blockIdx.x * 256 + threadIdx.x;
    float s = 0.f;
    #pragma unroll
    for (int z = 0; z < 8; z++) s += g_ct[(size_t)z * B_ * N_ + i];
    out[i] = s;
}

// ===========================================================================
extern "C" void kernel_launch(void* const* d_in, const int* in_sizes, int n_in,
                              void* d_out, int out_size)
{
    const float* s_t_hat = (const float*)d_in[0];
    const float* h       = (const float*)d_in[1];
    const float* mask    = (const float*)d_in[2];
    const float* cov     = (const float*)d_in[3];
    const float* q_h     = (const float*)d_in[4];
    const float* Wh      = (const float*)d_in[5];
    const float* Wq      = (const float*)d_in[6];
    const float* Wc      = (const float*)d_in[7];
    const float* Wd      = (const float*)d_in[8];
    const float* bd      = (const float*)d_in[9];
    const float* vw      = (const float*)d_in[10];
    float* out = (float*)d_out;

    static bool attr_set = false;
    if (!attr_set) {
        cudaFuncSetAttribute(scores_mma, cudaFuncAttributeMaxDynamicSharedMemorySize, SMEM_TOTAL);
        attr_set = true;
    }

    conv_a_kernel<<<16384, 256>>>(h, q_h);
    conv_b_kernel<<<2048, 256>>>(Wh, Wq);
    dec_kernel<<<dim3(32, 128), 256>>>(s_t_hat, Wd, bd);
    scores_mma<<<dim3(NPART, M_ / 128), 256, SMEM_TOTAL>>>(Wc, vw, cov);
    softmax_kernel<<<32, 256>>>(mask, cov, out);
    ct_part_kernel<<<dim3(32, N_ / 256, 8), 256>>>(h, out);
    ct_reduce_kernel<<<B_ * N_ / 256, 256>>>(out);
}

// round 10
// speedup vs baseline: 1.4365x; 1.0845x over previous
#include <cuda_runtime.h>
#include <cuda_fp16.h>
#include <math.h>
#include <stdint.h>

#define B_    32
#define TK_   2048
#define N_    1024
#define M_    (B_ * TK_)        // 65536
#define KTOT  2048
#define NPART 8                 // N_/128 column blocks -> score partials

// ---------------- scratch (no allocs allowed) ----------------
__device__ float g_dec[B_ * N_];
__device__ float g_part[NPART * M_];
__device__ float g_ct[8 * B_ * N_];
// pre-converted operands: A = [h|q] single fp16; B = [Wh|Wq] fp16 hi+lo split
__device__ __half g_A[(size_t)M_ * KTOT];
__device__ __half g_Bhi[(size_t)N_ * KTOT];
__device__ __half g_Blo[(size_t)N_ * KTOT];

// ---------------- smem layout (dynamic) ----------------
// K=64 per stage; fp16 tiles, row stride 72 elements (144B):
// 144 mod 128 = 16 -> 8 consecutive rows hit distinct 16B banks (ldmatrix clean)
#define ROWSTRIDE 144
#define A_OFF  0
#define BH_OFF 18432
#define BL_OFF 36864
#define STAGE_BYTES 55296
#define NSTAGE 3
#define EPI_DEC (NSTAGE * STAGE_BYTES)     // 165888
#define EPI_WC  (EPI_DEC + 512)
#define EPI_VW  (EPI_WC + 512)
#define EPI_COV (EPI_VW + 512)
#define EPI_RED (EPI_COV + 512)            // 128*16 floats = 8192B
#define SMEM_TOTAL (EPI_RED + 8192)        // 176128

__device__ __forceinline__ uint32_t smem_u32(const void* p) {
    uint32_t a;
    asm("{ .reg .u64 t; cvta.to.shared.u64 t, %1; cvt.u32.u64 %0, t; }" : "=r"(a) : "l"(p));
    return a;
}

// pack two fp32 into one uint32 holding fp16x2 (lo = x, hi = y)
__device__ __forceinline__ uint32_t pack_h2(float x, float y) {
    uint32_t r;
    asm("cvt.rn.f16x2.f32 %0, %1, %2;" : "=r"(r) : "f"(y), "f"(x));
    return r;
}

#define LDSM_X4(r0, r1, r2, r3, addr) \
    asm volatile("ldmatrix.sync.aligned.m8n8.x4.shared.b16 {%0,%1,%2,%3}, [%4];" \
                 : "=r"(r0), "=r"(r1), "=r"(r2), "=r"(r3) : "r"(addr))
#define MMA16816F16(d, a, b) \
    asm volatile("mma.sync.aligned.m16n8k16.row.col.f32.f16.f16.f32 " \
                 "{%0,%1,%2,%3}, {%4,%5,%6,%7}, {%8,%9}, {%0,%1,%2,%3};" \
                 : "+f"((d)[0]), "+f"((d)[1]), "+f"((d)[2]), "+f"((d)[3]) \
                 : "r"((a)[0]), "r"((a)[1]), "r"((a)[2]), "r"((a)[3]), \
                   "r"((b)[0]), "r"((b)[1]))
#define CP16(smaddr, gptr) \
    asm volatile("cp.async.cg.shared.global [%0], [%1], 16;" \
                 :: "r"(smaddr), "l"(gptr) : "memory")
#define CP_COMMIT() asm volatile("cp.async.commit_group;" ::: "memory")
#define CP_WAIT1()  asm volatile("cp.async.wait_group 1;" ::: "memory")

// ===========================================================================
// pre-conversion kernels
// ===========================================================================
__global__ __launch_bounds__(256) void conv_a_kernel(
    const float* __restrict__ h, const float* __restrict__ q)
{
    const size_t UN = (size_t)M_ * (N_ / 4);
    const size_t total = 2 * UN;
    for (size_t u = (size_t)blockIdx.x * 256 + threadIdx.x; u < total;
         u += (size_t)gridDim.x * 256) {
        const int t = (u >= UN) ? 1 : 0;
        const size_t v = u - (t ? UN : 0);
        const size_t m = v >> 8;
        const int seg = (int)(v & 255);
        float4 val = *(const float4*)((t ? q : h) + m * N_ + seg * 4);
        size_t d = m * (size_t)KTOT + (size_t)t * N_ + (size_t)seg * 4;
        *(uint2*)(g_A + d) = make_uint2(pack_h2(val.x, val.y), pack_h2(val.z, val.w));
    }
}

__global__ __launch_bounds__(256) void conv_b_kernel(
    const float* __restrict__ Wh, const float* __restrict__ Wq)
{
    const size_t UN = (size_t)N_ * (N_ / 4);
    const size_t total = 2 * UN;
    for (size_t u = (size_t)blockIdx.x * 256 + threadIdx.x; u < total;
         u += (size_t)gridDim.x * 256) {
        const int t = (u >= UN) ? 1 : 0;
        const size_t v = u - (t ? UN : 0);
        const size_t n = v >> 8;
        const int seg = (int)(v & 255);
        float4 val = *(const float4*)((t ? Wq : Wh) + n * N_ + seg * 4);
        float hx = __half2float(__float2half_rn(val.x));
        float hy = __half2float(__float2half_rn(val.y));
        float hz = __half2float(__float2half_rn(val.z));
        float hw = __half2float(__float2half_rn(val.w));
        size_t d = n * (size_t)KTOT + (size_t)t * N_ + (size_t)seg * 4;
        *(uint2*)(g_Bhi + d) = make_uint2(pack_h2(hx, hy), pack_h2(hz, hw));
        *(uint2*)(g_Blo + d) = make_uint2(pack_h2(val.x - hx, val.y - hy),
                                          pack_h2(val.z - hz, val.w - hw));
    }
}

// ===========================================================================
// dec_feat[b][m] = s_t_hat[b] . W_d[m] + b_d[m]
// ===========================================================================
__global__ __launch_bounds__(256) void dec_kernel(
    const float* __restrict__ s_t_hat,
    const float* __restrict__ Wd,
    const float* __restrict__ bd)
{
    int b    = blockIdx.x;
    int warp = threadIdx.x >> 5;
    int lane = threadIdx.x & 31;
    int m    = blockIdx.y * 8 + warp;

    const float* sp = s_t_hat + (size_t)b * N_;
    const float* wp = Wd + (size_t)m * N_;
    float acc = 0.f;
    #pragma unroll 4
    for (int k = lane; k < N_; k += 32) acc = fmaf(sp[k], wp[k], acc);
    #pragma unroll
    for (int o = 16; o > 0; o >>= 1) acc += __shfl_xor_sync(0xffffffffu, acc, o);
    if (lane == 0) g_dec[(size_t)b * N_ + m] = acc + bd[m];
}

// ===========================================================================
// scores via fp16 mma.sync, 2-term split (a*bh + a*bl).
// Block tile 128x128, 256 threads (8 warps, 2m x 4n, 64x32 per warp).
// K=64 per stage, NSTAGE=3 cp.async pipeline, 32 mainloop iterations.
// ===========================================================================
__global__ __launch_bounds__(256, 1) void scores_mma(
    const float* __restrict__ Wc, const float* __restrict__ vw,
    const float* __restrict__ cov)
{
    extern __shared__ char sm[];
    const uint32_t smem = smem_u32(sm);
    const int tid  = threadIdx.x;
    const int lane = tid & 31;
    const int wid  = tid >> 5;
    const int wm   = wid & 1;       // 2 m-groups of 64
    const int wn   = wid >> 1;      // 4 n-groups of 32
    const int mBase = blockIdx.y * 128;
    const int nBase = blockIdx.x * 128;
    const int b     = mBase >> 11;
    const int trow  = mBase & (TK_ - 1);

    float* dec_s = (float*)(sm + EPI_DEC);
    float* wc_s  = (float*)(sm + EPI_WC);
    float* vw_s  = (float*)(sm + EPI_VW);
    float* cov_s = (float*)(sm + EPI_COV);
    float* red   = (float*)(sm + EPI_RED);

    if (tid < 128) {
        dec_s[tid] = g_dec[(size_t)b * N_ + nBase + tid];
        wc_s[tid]  = Wc[nBase + tid];
        vw_s[tid]  = vw[nBase + tid];
        cov_s[tid] = cov[(size_t)b * TK_ + trow + tid];
    }

    // ldmatrix lane-address components
    const int g = lane >> 3;
    const uint32_t a_row = (uint32_t)(((g & 1) << 3) + (lane & 7));
    const uint32_t a_col = (uint32_t)((g >> 1) << 3);
    const uint32_t b4_n  = (uint32_t)((lane >> 4) << 3);        // 0 or 8
    const uint32_t b4_k  = (uint32_t)(((lane >> 3) & 1) << 3);  // 0 or 8
    const uint32_t b4_r  = (uint32_t)(lane & 7);

    // cp.async: unit u covers row u>>3 (0..127 over 4 j-steps), 16B-seg u&7
    const int crow = tid >> 3, cseg = tid & 7;

    float acc[4][4][4];
    #pragma unroll
    for (int mf = 0; mf < 4; mf++)
        #pragma unroll
        for (int nf = 0; nf < 4; nf++)
            #pragma unroll
            for (int x = 0; x < 4; x++) acc[mf][nf][x] = 0.f;

    auto cp_stage = [&](int ks, int st) {
        const uint32_t sbase = smem + st * STAGE_BYTES;
        const int k0 = ks * 64;
        #pragma unroll
        for (int j = 0; j < 4; j++) {
            const int row = crow + j * 32;
            const uint32_t soff = (uint32_t)(row * ROWSTRIDE + cseg * 16);
            const size_t ga = (size_t)(mBase + row) * KTOT + k0 + cseg * 8;
            const size_t gb = (size_t)(nBase + row) * KTOT + k0 + cseg * 8;
            CP16(sbase + A_OFF + soff, g_A + ga);
            CP16(sbase + BH_OFF + soff, g_Bhi + gb);
            CP16(sbase + BL_OFF + soff, g_Blo + gb);
        }
    };

    auto mma_step = [&](int st) {
        const uint32_t Ab  = smem + st * STAGE_BYTES + A_OFF;
        const uint32_t Bh  = smem + st * STAGE_BYTES + BH_OFF;
        const uint32_t Bl  = smem + st * STAGE_BYTES + BL_OFF;
        #pragma unroll
        for (int kf = 0; kf < 4; kf++) {
            uint32_t ah[4][4], bh[4][2], bl[4][2];
            #pragma unroll
            for (int mf = 0; mf < 4; mf++) {
                uint32_t off = (uint32_t)((wm * 64 + mf * 16 + a_row) * ROWSTRIDE
                                          + (kf * 16 + a_col) * 2);
                LDSM_X4(ah[mf][0], ah[mf][1], ah[mf][2], ah[mf][3], Ab + off);
            }
            #pragma unroll
            for (int np = 0; np < 2; np++) {
                uint32_t off = (uint32_t)((wn * 32 + np * 16 + b4_n + b4_r) * ROWSTRIDE
                                          + (kf * 16 + b4_k) * 2);
                LDSM_X4(bh[np*2][0], bh[np*2][1], bh[np*2+1][0], bh[np*2+1][1], Bh + off);
                LDSM_X4(bl[np*2][0], bl[np*2][1], bl[np*2+1][0], bl[np*2+1][1], Bl + off);
            }
            #pragma unroll
            for (int mf = 0; mf < 4; mf++)
                #pragma unroll
                for (int nf = 0; nf < 4; nf++) {
                    MMA16816F16(acc[mf][nf], ah[mf], bh[nf]);
                    MMA16816F16(acc[mf][nf], ah[mf], bl[nf]);
                }
        }
    };

    // prologue: fill NSTAGE-1 = 2 stages
    cp_stage(0, 0); CP_COMMIT();
    cp_stage(1, 1); CP_COMMIT();

    const int NKS = KTOT / 64;   // 32
    int cur = 0, nxt = 2;        // stage indices mod 3
    for (int ks = 0; ks < NKS; ks++) {
        CP_WAIT1();
        __syncthreads();
        const int pf = ks + 2;
        if (pf < NKS) cp_stage(pf, nxt);
        CP_COMMIT();
        mma_step(cur);
        cur = (cur == 2) ? 0 : cur + 1;
        nxt = (nxt == 2) ? 0 : nxt + 1;
    }

    // fused epilogue: tanh + dot with v_w, per-row partials
    #pragma unroll
    for (int mf = 0; mf < 4; mf++) {
        const int rA = wm * 64 + mf * 16 + (lane >> 2);
        const int rB = rA + 8;
        const float covA = cov_s[rA];
        const float covB = cov_s[rB];
        float sA = 0.f, sB = 0.f;
        #pragma unroll
        for (int nf = 0; nf < 4; nf++) {
            const int n0 = wn * 32 + nf * 8 + ((lane & 3) << 1);
            const float d0 = dec_s[n0],   d1 = dec_s[n0 + 1];
            const float w0 = wc_s[n0],    w1 = wc_s[n0 + 1];
            const float v0 = vw_s[n0],    v1 = vw_s[n0 + 1];
            sA += tanhf(acc[mf][nf][0] + d0 + covA * w0) * v0
                + tanhf(acc[mf][nf][1] + d1 + covA * w1) * v1;
            sB += tanhf(acc[mf][nf][2] + d0 + covB * w0) * v0
                + tanhf(acc[mf][nf][3] + d1 + covB * w1) * v1;
        }
        const int colslot = wn * 4 + (lane & 3);
        red[rA * 16 + colslot] = sA;
        red[rB * 16 + colslot] = sB;
    }
    __syncthreads();
    if (tid < 128) {
        float s = 0.f;
        #pragma unroll
        for (int x = 0; x < 16; x++) s += red[tid * 16 + x];
        g_part[(size_t)blockIdx.x * M_ + mBase + tid] = s;
    }
}

// ===========================================================================
// softmax with mask + renormalize; writes attn and coverage_out
// ===========================================================================
__global__ __launch_bounds__(256) void softmax_kernel(
    const float* __restrict__ mask,
    const float* __restrict__ cov,
    float* __restrict__ out)
{
    __shared__ float sh[TK_];
    __shared__ float red[256];
    const int b = blockIdx.x, tid = threadIdx.x;

    float lmax = -1e30f;
    for (int t = tid; t < TK_; t += 256) {
        float s = 0.f;
        #pragma unroll
        for (int c = 0; c < NPART; c++) s += g_part[(size_t)c * M_ + (size_t)b * TK_ + t];
        sh[t] = s;
        lmax = fmaxf(lmax, s);
    }
    red[tid] = lmax; __syncthreads();
    for (int o = 128; o > 0; o >>= 1) {
        if (tid < o) red[tid] = fmaxf(red[tid], red[tid + o]);
        __syncthreads();
    }
    const float mx = red[0];
    __syncthreads();

    float lsum = 0.f;
    for (int t = tid; t < TK_; t += 256) {
        float e = expf(sh[t] - mx) * mask[(size_t)b * TK_ + t];
        sh[t] = e;
        lsum += e;
    }
    red[tid] = lsum; __syncthreads();
    for (int o = 128; o > 0; o >>= 1) {
        if (tid < o) red[tid] += red[tid + o];
        __syncthreads();
    }
    const float inv = 1.f / red[0];

    for (int t = tid; t < TK_; t += 256) {
        float a = sh[t] * inv;
        out[(size_t)B_ * N_ + (size_t)b * TK_ + t] = a;
        out[(size_t)B_ * N_ + (size_t)B_ * TK_ + (size_t)b * TK_ + t] =
            cov[(size_t)b * TK_ + t] + a;
    }
}

// ===========================================================================
// c_t partials over 8 T-chunks, then reduce
// ===========================================================================
__global__ __launch_bounds__(256) void ct_part_kernel(
    const float* __restrict__ h,
    const float* __restrict__ out)
{
    __shared__ float ash[256];
    const int b = blockIdx.x;
    const int n = blockIdx.y * 256 + threadIdx.x;
    const int z = blockIdx.z;
    const float* attn = out + (size_t)B_ * N_ + (size_t)b * TK_ + z * 256;

    ash[threadIdx.x] = attn[threadIdx.x];
    __syncthreads();
    const float* hp = h + ((size_t)b * TK_ + z * 256) * N_ + n;
    float acc = 0.f;
    #pragma unroll 8
    for (int tt = 0; tt < 256; tt++)
        acc = fmaf(ash[tt], hp[(size_t)tt * N_], acc);
    g_ct[((size_t)z * B_ + b) * N_ + n] = acc;
}

__global__ __launch_bounds__(256) void ct_reduce_kernel(float* __restrict__ out)
{
    const int i = blockIdx.x * 256 + threadIdx.x;
    float s = 0.f;
    #pragma unroll
    for (int z = 0; z < 8; z++) s += g_ct[(size_t)z * B_ * N_ + i];
    out[i] = s;
}

// ===========================================================================
extern "C" void kernel_launch(void* const* d_in, const int* in_sizes, int n_in,
                              void* d_out, int out_size)
{
    const float* s_t_hat = (const float*)d_in[0];
    const float* h       = (const float*)d_in[1];
    const float* mask    = (const float*)d_in[2];
    const float* cov     = (const float*)d_in[3];
    const float* q_h     = (const float*)d_in[4];
    const float* Wh      = (const float*)d_in[5];
    const float* Wq      = (const float*)d_in[6];
    const float* Wc      = (const float*)d_in[7];
    const float* Wd      = (const float*)d_in[8];
    const float* bd      = (const float*)d_in[9];
    const float* vw      = (const float*)d_in[10];
    float* out = (float*)d_out;

    static bool attr_set = false;
    if (!attr_set) {
        cudaFuncSetAttribute(scores_mma, cudaFuncAttributeMaxDynamicSharedMemorySize, SMEM_TOTAL);
        attr_set = true;
    }

    conv_a_kernel<<<16384, 256>>>(h, q_h);
    conv_b_kernel<<<2048, 256>>>(Wh, Wq);
    dec_kernel<<<dim3(32, 128), 256>>>(s_t_hat, Wd, bd);
    scores_mma<<<dim3(NPART, M_ / 128), 256, SMEM_TOTAL>>>(Wc, vw, cov);
    softmax_kernel<<<32, 256>>>(mask, cov, out);
    ct_part_kernel<<<dim3(32, N_ / 256, 8), 256>>>(h, out);
    ct_reduce_kernel<<<B_ * N_ / 256, 256>>>(out);
}

// round 12
// speedup vs baseline: 1.4411x; 1.0032x over previous
#include <cuda_runtime.h>
#include <cuda_fp16.h>
#include <math.h>
#include <stdint.h>

#define B_    32
#define TK_   2048
#define N_    1024
#define M_    (B_ * TK_)        // 65536
#define KTOT  2048
#define NPART 8                 // N_/128 column blocks -> score partials

// ---------------- scratch (no allocs allowed) ----------------
__device__ float g_dec[B_ * N_];
__device__ float g_part[NPART * M_];
__device__ float g_ct[8 * B_ * N_];
// pre-converted operands: A = [h|q] single fp16; B = [Wh|Wq] fp16 hi+lo split
__device__ __half g_A[(size_t)M_ * KTOT];
__device__ __half g_Bhi[(size_t)N_ * KTOT];
__device__ __half g_Blo[(size_t)N_ * KTOT];

// ---------------- smem layout (dynamic) ----------------
// K=64 per stage; fp16 tiles, row stride 72 elements (144B):
// 144 mod 128 = 16 -> 8 consecutive rows hit distinct 16B banks (ldmatrix clean)
#define ROWSTRIDE 144
#define A_OFF  0
#define BH_OFF 18432
#define BL_OFF 36864
#define STAGE_BYTES 55296
#define NSTAGE 3
#define EPI_DEC (NSTAGE * STAGE_BYTES)     // 165888
#define EPI_WC  (EPI_DEC + 512)
#define EPI_VW  (EPI_WC + 512)
#define EPI_COV (EPI_VW + 512)
#define EPI_RED (EPI_COV + 512)            // 128*16 floats = 8192B
#define SMEM_TOTAL (EPI_RED + 8192)        // 176128

__device__ __forceinline__ uint32_t smem_u32(const void* p) {
    uint32_t a;
    asm("{ .reg .u64 t; cvta.to.shared.u64 t, %1; cvt.u32.u64 %0, t; }" : "=r"(a) : "l"(p));
    return a;
}

// pack two fp32 into one uint32 holding fp16x2 (lo = x, hi = y)
__device__ __forceinline__ uint32_t pack_h2(float x, float y) {
    uint32_t r;
    asm("cvt.rn.f16x2.f32 %0, %1, %2;" : "=r"(r) : "f"(y), "f"(x));
    return r;
}

#define LDSM_X4(r0, r1, r2, r3, addr) \
    asm volatile("ldmatrix.sync.aligned.m8n8.x4.shared.b16 {%0,%1,%2,%3}, [%4];" \
                 : "=r"(r0), "=r"(r1), "=r"(r2), "=r"(r3) : "r"(addr))
#define MMA16816F16(d, a, b) \
    asm volatile("mma.sync.aligned.m16n8k16.row.col.f32.f16.f16.f32 " \
                 "{%0,%1,%2,%3}, {%4,%5,%6,%7}, {%8,%9}, {%0,%1,%2,%3};" \
                 : "+f"((d)[0]), "+f"((d)[1]), "+f"((d)[2]), "+f"((d)[3]) \
                 : "r"((a)[0]), "r"((a)[1]), "r"((a)[2]), "r"((a)[3]), \
                   "r"((b)[0]), "r"((b)[1]))
#define CP16(smaddr, gptr) \
    asm volatile("cp.async.cg.shared.global [%0], [%1], 16;" \
                 :: "r"(smaddr), "l"(gptr) : "memory")
#define CP_COMMIT() asm volatile("cp.async.commit_group;" ::: "memory")
#define CP_WAIT1()  asm volatile("cp.async.wait_group 1;" ::: "memory")

// ===========================================================================
// pre-conversion kernels
// ===========================================================================
__global__ __launch_bounds__(256) void conv_a_kernel(
    const float* __restrict__ h, const float* __restrict__ q)
{
    const size_t UN = (size_t)M_ * (N_ / 4);
    const size_t total = 2 * UN;
    for (size_t u = (size_t)blockIdx.x * 256 + threadIdx.x; u < total;
         u += (size_t)gridDim.x * 256) {
        const int t = (u >= UN) ? 1 : 0;
        const size_t v = u - (t ? UN : 0);
        const size_t m = v >> 8;
        const int seg = (int)(v & 255);
        float4 val = *(const float4*)((t ? q : h) + m * N_ + seg * 4);
        size_t d = m * (size_t)KTOT + (size_t)t * N_ + (size_t)seg * 4;
        *(uint2*)(g_A + d) = make_uint2(pack_h2(val.x, val.y), pack_h2(val.z, val.w));
    }
}

__global__ __launch_bounds__(256) void conv_b_kernel(
    const float* __restrict__ Wh, const float* __restrict__ Wq)
{
    const size_t UN = (size_t)N_ * (N_ / 4);
    const size_t total = 2 * UN;
    for (size_t u = (size_t)blockIdx.x * 256 + threadIdx.x; u < total;
         u += (size_t)gridDim.x * 256) {
        const int t = (u >= UN) ? 1 : 0;
        const size_t v = u - (t ? UN : 0);
        const size_t n = v >> 8;
        const int seg = (int)(v & 255);
        float4 val = *(const float4*)((t ? Wq : Wh) + n * N_ + seg * 4);
        float hx = __half2float(__float2half_rn(val.x));
        float hy = __half2float(__float2half_rn(val.y));
        float hz = __half2float(__float2half_rn(val.z));
        float hw = __half2float(__float2half_rn(val.w));
        size_t d = n * (size_t)KTOT + (size_t)t * N_ + (size_t)seg * 4;
        *(uint2*)(g_Bhi + d) = make_uint2(pack_h2(hx, hy), pack_h2(hz, hw));
        *(uint2*)(g_Blo + d) = make_uint2(pack_h2(val.x - hx, val.y - hy),
                                          pack_h2(val.z - hz, val.w - hw));
    }
}

// ===========================================================================
// dec_feat[b][m] = s_t_hat[b] . W_d[m] + b_d[m]
// ===========================================================================
__global__ __launch_bounds__(256) void dec_kernel(
    const float* __restrict__ s_t_hat,
    const float* __restrict__ Wd,
    const float* __restrict__ bd)
{
    int b    = blockIdx.x;
    int warp = threadIdx.x >> 5;
    int lane = threadIdx.x & 31;
    int m    = blockIdx.y * 8 + warp;

    const float* sp = s_t_hat + (size_t)b * N_;
    const float* wp = Wd + (size_t)m * N_;
    float acc = 0.f;
    #pragma unroll 4
    for (int k = lane; k < N_; k += 32) acc = fmaf(sp[k], wp[k], acc);
    #pragma unroll
    for (int o = 16; o > 0; o >>= 1) acc += __shfl_xor_sync(0xffffffffu, acc, o);
    if (lane == 0) g_dec[(size_t)b * N_ + m] = acc + bd[m];
}

// ===========================================================================
// scores via fp16 mma.sync, 2-term split (a*bh + a*bl).
// Block tile 128x128, 256 threads (8 warps, 2m x 4n, 64x32 per warp).
// K=64 per stage, NSTAGE=3 cp.async pipeline, register double-buffered
// fragments across kf (LDSM for kf+1 issued before MMAs of kf).
// ===========================================================================
__global__ __launch_bounds__(256, 1) void scores_mma(
    const float* __restrict__ Wc, const float* __restrict__ vw,
    const float* __restrict__ cov)
{
    extern __shared__ char sm[];
    const uint32_t smem = smem_u32(sm);
    const int tid  = threadIdx.x;
    const int lane = tid & 31;
    const int wid  = tid >> 5;
    const int wm   = wid & 1;       // 2 m-groups of 64
    const int wn   = wid >> 1;      // 4 n-groups of 32
    const int mBase = blockIdx.y * 128;
    const int nBase = blockIdx.x * 128;
    const int b     = mBase >> 11;
    const int trow  = mBase & (TK_ - 1);

    float* dec_s = (float*)(sm + EPI_DEC);
    float* wc_s  = (float*)(sm + EPI_WC);
    float* vw_s  = (float*)(sm + EPI_VW);
    float* cov_s = (float*)(sm + EPI_COV);
    float* red   = (float*)(sm + EPI_RED);

    if (tid < 128) {
        dec_s[tid] = g_dec[(size_t)b * N_ + nBase + tid];
        wc_s[tid]  = Wc[nBase + tid];
        vw_s[tid]  = vw[nBase + tid];
        cov_s[tid] = cov[(size_t)b * TK_ + trow + tid];
    }

    // ldmatrix lane-address components
    const int g = lane >> 3;
    const uint32_t a_row = (uint32_t)(((g & 1) << 3) + (lane & 7));
    const uint32_t a_col = (uint32_t)((g >> 1) << 3);
    const uint32_t b4_n  = (uint32_t)((lane >> 4) << 3);        // 0 or 8
    const uint32_t b4_k  = (uint32_t)(((lane >> 3) & 1) << 3);  // 0 or 8
    const uint32_t b4_r  = (uint32_t)(lane & 7);

    // cp.async: unit u covers row u>>3 (0..127 over 4 j-steps), 16B-seg u&7
    const int crow = tid >> 3, cseg = tid & 7;

    float acc[4][4][4];
    #pragma unroll
    for (int mf = 0; mf < 4; mf++)
        #pragma unroll
        for (int nf = 0; nf < 4; nf++)
            #pragma unroll
            for (int x = 0; x < 4; x++) acc[mf][nf][x] = 0.f;

    auto cp_stage = [&](int ks, int st) {
        const uint32_t sbase = smem + st * STAGE_BYTES;
        const int k0 = ks * 64;
        #pragma unroll
        for (int j = 0; j < 4; j++) {
            const int row = crow + j * 32;
            const uint32_t soff = (uint32_t)(row * ROWSTRIDE + cseg * 16);
            const size_t ga = (size_t)(mBase + row) * KTOT + k0 + cseg * 8;
            const size_t gb = (size_t)(nBase + row) * KTOT + k0 + cseg * 8;
            CP16(sbase + A_OFF + soff, g_A + ga);
            CP16(sbase + BH_OFF + soff, g_Bhi + gb);
            CP16(sbase + BL_OFF + soff, g_Blo + gb);
        }
    };

    // fragment loader: stage st, k-fraction kf -> registers
    auto load_frag = [&](int st, int kf,
                         uint32_t (&ah)[4][4], uint32_t (&bh)[4][2], uint32_t (&bl)[4][2]) {
        const uint32_t Ab = smem + st * STAGE_BYTES + A_OFF;
        const uint32_t Bh = smem + st * STAGE_BYTES + BH_OFF;
        const uint32_t Bl = smem + st * STAGE_BYTES + BL_OFF;
        #pragma unroll
        for (int mf = 0; mf < 4; mf++) {
            uint32_t off = (uint32_t)((wm * 64 + mf * 16 + a_row) * ROWSTRIDE
                                      + (kf * 16 + a_col) * 2);
            LDSM_X4(ah[mf][0], ah[mf][1], ah[mf][2], ah[mf][3], Ab + off);
        }
        #pragma unroll
        for (int np = 0; np < 2; np++) {
            uint32_t off = (uint32_t)((wn * 32 + np * 16 + b4_n + b4_r) * ROWSTRIDE
                                      + (kf * 16 + b4_k) * 2);
            LDSM_X4(bh[np*2][0], bh[np*2][1], bh[np*2+1][0], bh[np*2+1][1], Bh + off);
            LDSM_X4(bl[np*2][0], bl[np*2][1], bl[np*2+1][0], bl[np*2+1][1], Bl + off);
        }
    };

    auto mma_frag = [&](uint32_t (&ah)[4][4], uint32_t (&bh)[4][2], uint32_t (&bl)[4][2]) {
        #pragma unroll
        for (int mf = 0; mf < 4; mf++)
            #pragma unroll
            for (int nf = 0; nf < 4; nf++) {
                MMA16816F16(acc[mf][nf], ah[mf], bh[nf]);
                MMA16816F16(acc[mf][nf], ah[mf], bl[nf]);
            }
    };

    // prologue: fill NSTAGE-1 = 2 stages
    cp_stage(0, 0); CP_COMMIT();
    cp_stage(1, 1); CP_COMMIT();

    uint32_t ahf[2][4][4], bhf[2][4][2], blf[2][4][2];

    const int NKS = KTOT / 64;   // 32
    int cur = 0, nxt = 2;        // stage indices mod 3
    for (int ks = 0; ks < NKS; ks++) {
        CP_WAIT1();
        __syncthreads();
        const int pf = ks + 2;
        if (pf < NKS) cp_stage(pf, nxt);
        CP_COMMIT();

        // register-pipelined kf loop: load kf+1 before issuing kf's MMAs
        load_frag(cur, 0, ahf[0], bhf[0], blf[0]);
        #pragma unroll
        for (int kf = 0; kf < 4; kf++) {
            if (kf < 3)
                load_frag(cur, kf + 1, ahf[(kf + 1) & 1], bhf[(kf + 1) & 1], blf[(kf + 1) & 1]);
            mma_frag(ahf[kf & 1], bhf[kf & 1], blf[kf & 1]);
        }

        cur = (cur == 2) ? 0 : cur + 1;
        nxt = (nxt == 2) ? 0 : nxt + 1;
    }

    // fused epilogue: tanh + dot with v_w, per-row partials
    #pragma unroll
    for (int mf = 0; mf < 4; mf++) {
        const int rA = wm * 64 + mf * 16 + (lane >> 2);
        const int rB = rA + 8;
        const float covA = cov_s[rA];
        const float covB = cov_s[rB];
        float sA = 0.f, sB = 0.f;
        #pragma unroll
        for (int nf = 0; nf < 4; nf++) {
            const int n0 = wn * 32 + nf * 8 + ((lane & 3) << 1);
            const float d0 = dec_s[n0],   d1 = dec_s[n0 + 1];
            const float w0 = wc_s[n0],    w1 = wc_s[n0 + 1];
            const float v0 = vw_s[n0],    v1 = vw_s[n0 + 1];
            sA += tanhf(acc[mf][nf][0] + d0 + covA * w0) * v0
                + tanhf(acc[mf][nf][1] + d1 + covA * w1) * v1;
            sB += tanhf(acc[mf][nf][2] + d0 + covB * w0) * v0
                + tanhf(acc[mf][nf][3] + d1 + covB * w1) * v1;
        }
        const int colslot = wn * 4 + (lane & 3);
        red[rA * 16 + colslot] = sA;
        red[rB * 16 + colslot] = sB;
    }
    __syncthreads();
    if (tid < 128) {
        float s = 0.f;
        #pragma unroll
        for (int x = 0; x < 16; x++) s += red[tid * 16 + x];
        g_part[(size_t)blockIdx.x * M_ + mBase + tid] = s;
    }
}

// ===========================================================================
// softmax with mask + renormalize; writes attn and coverage_out
// ===========================================================================
__global__ __launch_bounds__(256) void softmax_kernel(
    const float* __restrict__ mask,
    const float* __restrict__ cov,
    float* __restrict__ out)
{
    __shared__ float sh[TK_];
    __shared__ float red[256];
    const int b = blockIdx.x, tid = threadIdx.x;

    float lmax = -1e30f;
    for (int t = tid; t < TK_; t += 256) {
        float s = 0.f;
        #pragma unroll
        for (int c = 0; c < NPART; c++) s += g_part[(size_t)c * M_ + (size_t)b * TK_ + t];
        sh[t] = s;
        lmax = fmaxf(lmax, s);
    }
    red[tid] = lmax; __syncthreads();
    for (int o = 128; o > 0; o >>= 1) {
        if (tid < o) red[tid] = fmaxf(red[tid], red[tid + o]);
        __syncthreads();
    }
    const float mx = red[0];
    __syncthreads();

    float lsum = 0.f;
    for (int t = tid; t < TK_; t += 256) {
        float e = expf(sh[t] - mx) * mask[(size_t)b * TK_ + t];
        sh[t] = e;
        lsum += e;
    }
    red[tid] = lsum; __syncthreads();
    for (int o = 128; o > 0; o >>= 1) {
        if (tid < o) red[tid] += red[tid + o];
        __syncthreads();
    }
    const float inv = 1.f / red[0];

    for (int t = tid; t < TK_; t += 256) {
        float a = sh[t] * inv;
        out[(size_t)B_ * N_ + (size_t)b * TK_ + t] = a;
        out[(size_t)B_ * N_ + (size_t)B_ * TK_ + (size_t)b * TK_ + t] =
            cov[(size_t)b * TK_ + t] + a;
    }
}

// ===========================================================================
// c_t partials over 8 T-chunks, then reduce
// ===========================================================================
__global__ __launch_bounds__(256) void ct_part_kernel(
    const float* __restrict__ h,
    const float* __restrict__ out)
{
    __shared__ float ash[256];
    const int b = blockIdx.x;
    const int n = blockIdx.y * 256 + threadIdx.x;
    const int z = blockIdx.z;
    const float* attn = out + (size_t)B_ * N_ + (size_t)b * TK_ + z * 256;

    ash[threadIdx.x] = attn[threadIdx.x];
    __syncthreads();
    const float* hp = h + ((size_t)b * TK_ + z * 256) * N_ + n;
    float acc = 0.f;
    #pragma unroll 8
    for (int tt = 0; tt < 256; tt++)
        acc = fmaf(ash[tt], hp[(size_t)tt * N_], acc);
    g_ct[((size_t)z * B_ + b) * N_ + n] = acc;
}

__global__ __launch_bounds__(256) void ct_reduce_kernel(float* __restrict__ out)
{
    const int i = blockIdx.x * 256 + threadIdx.x;
    float s = 0.f;
    #pragma unroll
    for (int z = 0; z < 8; z++) s += g_ct[(size_t)z * B_ * N_ + i];
    out[i] = s;
}

// ===========================================================================
extern "C" void kernel_launch(void* const* d_in, const int* in_sizes, int n_in,
                              void* d_out, int out_size)
{
    const float* s_t_hat = (const float*)d_in[0];
    const float* h       = (const float*)d_in[1];
    const float* mask    = (const float*)d_in[2];
    const float* cov     = (const float*)d_in[3];
    const float* q_h     = (const float*)d_in[4];
    const float* Wh      = (const float*)d_in[5];
    const float* Wq      = (const float*)d_in[6];
    const float* Wc      = (const float*)d_in[7];
    const float* Wd      = (const float*)d_in[8];
    const float* bd      = (const float*)d_in[9];
    const float* vw      = (const float*)d_in[10];
    float* out = (float*)d_out;

    static bool attr_set = false;
    if (!attr_set) {
        cudaFuncSetAttribute(scores_mma, cudaFuncAttributeMaxDynamicSharedMemorySize, SMEM_TOTAL);
        attr_set = true;
    }

    conv_a_kernel<<<16384, 256>>>(h, q_h);
    conv_b_kernel<<<2048, 256>>>(Wh, Wq);
    dec_kernel<<<dim3(32, 128), 256>>>(s_t_hat, Wd, bd);
    scores_mma<<<dim3(NPART, M_ / 128), 256, SMEM_TOTAL>>>(Wc, vw, cov);
    softmax_kernel<<<32, 256>>>(mask, cov, out);
    ct_part_kernel<<<dim3(32, N_ / 256, 8), 256>>>(h, out);
    ct_reduce_kernel<<<B_ * N_ / 256, 256>>>(out);
}

// round 13
// speedup vs baseline: 2.2257x; 1.5444x over previous
#include <cuda_runtime.h>
#include <cuda_fp16.h>
#include <math.h>
#include <stdint.h>

#define B_    32
#define TK_   2048
#define N_    1024
#define M_    (B_ * TK_)        // 65536
#define KTOT  2048
#define NPART 8                 // N_/128 column blocks -> score partials

// ---------------- scratch (no allocs allowed) ----------------
__device__ float g_dec[B_ * N_];
__device__ float g_part[NPART * M_];
__device__ float g_ct[8 * B_ * N_];
// pre-converted fp16 operands: A = [h|q], B = [Wh|Wq], K-fused layout
__device__ __half g_A[(size_t)M_ * KTOT];
__device__ __half g_B[(size_t)N_ * KTOT];

// ---------------- smem layout (dynamic) ----------------
// K=64 per stage; fp16 tiles, row stride 72 elements (144B):
// 144 mod 128 = 16 -> 8 consecutive rows hit distinct 16B banks (ldmatrix clean)
#define ROWSTRIDE 144
#define A_OFF  0
#define B_OFF  18432
#define STAGE_BYTES 36864
#define NSTAGE 4
#define EPI_DEC (NSTAGE * STAGE_BYTES)     // 147456
#define EPI_WC  (EPI_DEC + 512)
#define EPI_VW  (EPI_WC + 512)
#define EPI_COV (EPI_VW + 512)
#define EPI_RED (EPI_COV + 512)            // 128*16 floats = 8192B
#define SMEM_TOTAL (EPI_RED + 8192)        // 157696

__device__ __forceinline__ uint32_t smem_u32(const void* p) {
    uint32_t a;
    asm("{ .reg .u64 t; cvta.to.shared.u64 t, %1; cvt.u32.u64 %0, t; }" : "=r"(a) : "l"(p));
    return a;
}

// pack two fp32 into one uint32 holding fp16x2 (lo = x, hi = y)
__device__ __forceinline__ uint32_t pack_h2(float x, float y) {
    uint32_t r;
    asm("cvt.rn.f16x2.f32 %0, %1, %2;" : "=r"(r) : "f"(y), "f"(x));
    return r;
}

#define LDSM_X4(r0, r1, r2, r3, addr) \
    asm volatile("ldmatrix.sync.aligned.m8n8.x4.shared.b16 {%0,%1,%2,%3}, [%4];" \
                 : "=r"(r0), "=r"(r1), "=r"(r2), "=r"(r3) : "r"(addr))
#define MMA16816F16(d, a, b) \
    asm volatile("mma.sync.aligned.m16n8k16.row.col.f32.f16.f16.f32 " \
                 "{%0,%1,%2,%3}, {%4,%5,%6,%7}, {%8,%9}, {%0,%1,%2,%3};" \
                 : "+f"((d)[0]), "+f"((d)[1]), "+f"((d)[2]), "+f"((d)[3]) \
                 : "r"((a)[0]), "r"((a)[1]), "r"((a)[2]), "r"((a)[3]), \
                   "r"((b)[0]), "r"((b)[1]))
#define CP16(smaddr, gptr) \
    asm volatile("cp.async.cg.shared.global [%0], [%1], 16;" \
                 :: "r"(smaddr), "l"(gptr) : "memory")
#define CP_COMMIT() asm volatile("cp.async.commit_group;" ::: "memory")
#define CP_WAIT2()  asm volatile("cp.async.wait_group 2;" ::: "memory")

// ===========================================================================
// pre-conversion kernels (plain fp32 -> fp16)
// ===========================================================================
__global__ __launch_bounds__(256) void conv_a_kernel(
    const float* __restrict__ h, const float* __restrict__ q)
{
    const size_t UN = (size_t)M_ * (N_ / 4);
    const size_t total = 2 * UN;
    for (size_t u = (size_t)blockIdx.x * 256 + threadIdx.x; u < total;
         u += (size_t)gridDim.x * 256) {
        const int t = (u >= UN) ? 1 : 0;
        const size_t v = u - (t ? UN : 0);
        const size_t m = v >> 8;
        const int seg = (int)(v & 255);
        float4 val = *(const float4*)((t ? q : h) + m * N_ + seg * 4);
        size_t d = m * (size_t)KTOT + (size_t)t * N_ + (size_t)seg * 4;
        *(uint2*)(g_A + d) = make_uint2(pack_h2(val.x, val.y), pack_h2(val.z, val.w));
    }
}

__global__ __launch_bounds__(256) void conv_b_kernel(
    const float* __restrict__ Wh, const float* __restrict__ Wq)
{
    const size_t UN = (size_t)N_ * (N_ / 4);
    const size_t total = 2 * UN;
    for (size_t u = (size_t)blockIdx.x * 256 + threadIdx.x; u < total;
         u += (size_t)gridDim.x * 256) {
        const int t = (u >= UN) ? 1 : 0;
        const size_t v = u - (t ? UN : 0);
        const size_t n = v >> 8;
        const int seg = (int)(v & 255);
        float4 val = *(const float4*)((t ? Wq : Wh) + n * N_ + seg * 4);
        size_t d = n * (size_t)KTOT + (size_t)t * N_ + (size_t)seg * 4;
        *(uint2*)(g_B + d) = make_uint2(pack_h2(val.x, val.y), pack_h2(val.z, val.w));
    }
}

// ===========================================================================
// dec_feat[b][m] = s_t_hat[b] . W_d[m] + b_d[m]
// ===========================================================================
__global__ __launch_bounds__(256) void dec_kernel(
    const float* __restrict__ s_t_hat,
    const float* __restrict__ Wd,
    const float* __restrict__ bd)
{
    int b    = blockIdx.x;
    int warp = threadIdx.x >> 5;
    int lane = threadIdx.x & 31;
    int m    = blockIdx.y * 8 + warp;

    const float* sp = s_t_hat + (size_t)b * N_;
    const float* wp = Wd + (size_t)m * N_;
    float acc = 0.f;
    #pragma unroll 4
    for (int k = lane; k < N_; k += 32) acc = fmaf(sp[k], wp[k], acc);
    #pragma unroll
    for (int o = 16; o > 0; o >>= 1) acc += __shfl_xor_sync(0xffffffffu, acc, o);
    if (lane == 0) g_dec[(size_t)b * N_ + m] = acc + bd[m];
}

// ===========================================================================
// scores via plain fp16 mma.sync (fp32 accum).
// Block tile 128x128, 256 threads (8 warps, 2m x 4n, 64x32 per warp).
// K=64 per stage, NSTAGE=4 cp.async pipeline, reg double-buffered fragments.
// ===========================================================================
__global__ __launch_bounds__(256, 1) void scores_mma(
    const float* __restrict__ Wc, const float* __restrict__ vw,
    const float* __restrict__ cov)
{
    extern __shared__ char sm[];
    const uint32_t smem = smem_u32(sm);
    const int tid  = threadIdx.x;
    const int lane = tid & 31;
    const int wid  = tid >> 5;
    const int wm   = wid & 1;       // 2 m-groups of 64
    const int wn   = wid >> 1;      // 4 n-groups of 32
    const int mBase = blockIdx.y * 128;
    const int nBase = blockIdx.x * 128;
    const int b     = mBase >> 11;
    const int trow  = mBase & (TK_ - 1);

    float* dec_s = (float*)(sm + EPI_DEC);
    float* wc_s  = (float*)(sm + EPI_WC);
    float* vw_s  = (float*)(sm + EPI_VW);
    float* cov_s = (float*)(sm + EPI_COV);
    float* red   = (float*)(sm + EPI_RED);

    if (tid < 128) {
        dec_s[tid] = g_dec[(size_t)b * N_ + nBase + tid];
        wc_s[tid]  = Wc[nBase + tid];
        vw_s[tid]  = vw[nBase + tid];
        cov_s[tid] = cov[(size_t)b * TK_ + trow + tid];
    }

    // ldmatrix lane-address components
    const int g = lane >> 3;
    const uint32_t a_row = (uint32_t)(((g & 1) << 3) + (lane & 7));
    const uint32_t a_col = (uint32_t)((g >> 1) << 3);
    const uint32_t b4_n  = (uint32_t)((lane >> 4) << 3);        // 0 or 8
    const uint32_t b4_k  = (uint32_t)(((lane >> 3) & 1) << 3);  // 0 or 8
    const uint32_t b4_r  = (uint32_t)(lane & 7);

    // cp.async: unit u covers row u>>3 (0..127 over 4 j-steps), 16B-seg u&7
    const int crow = tid >> 3, cseg = tid & 7;

    float acc[4][4][4];
    #pragma unroll
    for (int mf = 0; mf < 4; mf++)
        #pragma unroll
        for (int nf = 0; nf < 4; nf++)
            #pragma unroll
            for (int x = 0; x < 4; x++) acc[mf][nf][x] = 0.f;

    auto cp_stage = [&](int ks, int st) {
        const uint32_t sbase = smem + st * STAGE_BYTES;
        const int k0 = ks * 64;
        #pragma unroll
        for (int j = 0; j < 4; j++) {
            const int row = crow + j * 32;
            const uint32_t soff = (uint32_t)(row * ROWSTRIDE + cseg * 16);
            const size_t ga = (size_t)(mBase + row) * KTOT + k0 + cseg * 8;
            const size_t gb = (size_t)(nBase + row) * KTOT + k0 + cseg * 8;
            CP16(sbase + A_OFF + soff, g_A + ga);
            CP16(sbase + B_OFF + soff, g_B + gb);
        }
    };

    // fragment loader: stage st, k-fraction kf -> registers
    auto load_frag = [&](int st, int kf,
                         uint32_t (&ah)[4][4], uint32_t (&bh)[4][2]) {
        const uint32_t Ab = smem + st * STAGE_BYTES + A_OFF;
        const uint32_t Bb = smem + st * STAGE_BYTES + B_OFF;
        #pragma unroll
        for (int mf = 0; mf < 4; mf++) {
            uint32_t off = (uint32_t)((wm * 64 + mf * 16 + a_row) * ROWSTRIDE
                                      + (kf * 16 + a_col) * 2);
            LDSM_X4(ah[mf][0], ah[mf][1], ah[mf][2], ah[mf][3], Ab + off);
        }
        #pragma unroll
        for (int np = 0; np < 2; np++) {
            uint32_t off = (uint32_t)((wn * 32 + np * 16 + b4_n + b4_r) * ROWSTRIDE
                                      + (kf * 16 + b4_k) * 2);
            LDSM_X4(bh[np*2][0], bh[np*2][1], bh[np*2+1][0], bh[np*2+1][1], Bb + off);
        }
    };

    auto mma_frag = [&](uint32_t (&ah)[4][4], uint32_t (&bh)[4][2]) {
        #pragma unroll
        for (int mf = 0; mf < 4; mf++)
            #pragma unroll
            for (int nf = 0; nf < 4; nf++)
                MMA16816F16(acc[mf][nf], ah[mf], bh[nf]);
    };

    // prologue: fill NSTAGE-1 = 3 stages
    cp_stage(0, 0); CP_COMMIT();
    cp_stage(1, 1); CP_COMMIT();
    cp_stage(2, 2); CP_COMMIT();

    uint32_t ahf[2][4][4], bhf[2][4][2];

    const int NKS = KTOT / 64;   // 32
    for (int ks = 0; ks < NKS; ks++) {
        CP_WAIT2();
        __syncthreads();
        const int pf = ks + NSTAGE - 1;
        if (pf < NKS) cp_stage(pf, pf & (NSTAGE - 1));
        CP_COMMIT();

        const int cur = ks & (NSTAGE - 1);
        load_frag(cur, 0, ahf[0], bhf[0]);
        #pragma unroll
        for (int kf = 0; kf < 4; kf++) {
            if (kf < 3)
                load_frag(cur, kf + 1, ahf[(kf + 1) & 1], bhf[(kf + 1) & 1]);
            mma_frag(ahf[kf & 1], bhf[kf & 1]);
        }
    }

    // fused epilogue: tanh + dot with v_w, per-row partials
    #pragma unroll
    for (int mf = 0; mf < 4; mf++) {
        const int rA = wm * 64 + mf * 16 + (lane >> 2);
        const int rB = rA + 8;
        const float covA = cov_s[rA];
        const float covB = cov_s[rB];
        float sA = 0.f, sB = 0.f;
        #pragma unroll
        for (int nf = 0; nf < 4; nf++) {
            const int n0 = wn * 32 + nf * 8 + ((lane & 3) << 1);
            const float d0 = dec_s[n0],   d1 = dec_s[n0 + 1];
            const float w0 = wc_s[n0],    w1 = wc_s[n0 + 1];
            const float v0 = vw_s[n0],    v1 = vw_s[n0 + 1];
            sA += tanhf(acc[mf][nf][0] + d0 + covA * w0) * v0
                + tanhf(acc[mf][nf][1] + d1 + covA * w1) * v1;
            sB += tanhf(acc[mf][nf][2] + d0 + covB * w0) * v0
                + tanhf(acc[mf][nf][3] + d1 + covB * w1) * v1;
        }
        const int colslot = wn * 4 + (lane & 3);
        red[rA * 16 + colslot] = sA;
        red[rB * 16 + colslot] = sB;
    }
    __syncthreads();
    if (tid < 128) {
        float s = 0.f;
        #pragma unroll
        for (int x = 0; x < 16; x++) s += red[tid * 16 + x];
        g_part[(size_t)blockIdx.x * M_ + mBase + tid] = s;
    }
}

// ===========================================================================
// softmax with mask + renormalize; writes attn and coverage_out
// ===========================================================================
__global__ __launch_bounds__(256) void softmax_kernel(
    const float* __restrict__ mask,
    const float* __restrict__ cov,
    float* __restrict__ out)
{
    __shared__ float sh[TK_];
    __shared__ float red[256];
    const int b = blockIdx.x, tid = threadIdx.x;

    float lmax = -1e30f;
    for (int t = tid; t < TK_; t += 256) {
        float s = 0.f;
        #pragma unroll
        for (int c = 0; c < NPART; c++) s += g_part[(size_t)c * M_ + (size_t)b * TK_ + t];
        sh[t] = s;
        lmax = fmaxf(lmax, s);
    }
    red[tid] = lmax; __syncthreads();
    for (int o = 128; o > 0; o >>= 1) {
        if (tid < o) red[tid] = fmaxf(red[tid], red[tid + o]);
        __syncthreads();
    }
    const float mx = red[0];
    __syncthreads();

    float lsum = 0.f;
    for (int t = tid; t < TK_; t += 256) {
        float e = expf(sh[t] - mx) * mask[(size_t)b * TK_ + t];
        sh[t] = e;
        lsum += e;
    }
    red[tid] = lsum; __syncthreads();
    for (int o = 128; o > 0; o >>= 1) {
        if (tid < o) red[tid] += red[tid + o];
        __syncthreads();
    }
    const float inv = 1.f / red[0];

    for (int t = tid; t < TK_; t += 256) {
        float a = sh[t] * inv;
        out[(size_t)B_ * N_ + (size_t)b * TK_ + t] = a;
        out[(size_t)B_ * N_ + (size_t)B_ * TK_ + (size_t)b * TK_ + t] =
            cov[(size_t)b * TK_ + t] + a;
    }
}

// ===========================================================================
// c_t partials over 8 T-chunks, then reduce
// ===========================================================================
__global__ __launch_bounds__(256) void ct_part_kernel(
    const float* __restrict__ h,
    const float* __restrict__ out)
{
    __shared__ float ash[256];
    const int b = blockIdx.x;
    const int n = blockIdx.y * 256 + threadIdx.x;
    const int z = blockIdx.z;
    const float* attn = out + (size_t)B_ * N_ + (size_t)b * TK_ + z * 256;

    ash[threadIdx.x] = attn[threadIdx.x];
    __syncthreads();
    const float* hp = h + ((size_t)b * TK_ + z * 256) * N_ + n;
    float acc = 0.f;
    #pragma unroll 8
    for (int tt = 0; tt < 256; tt++)
        acc = fmaf(ash[tt], hp[(size_t)tt * N_], acc);
    g_ct[((size_t)z * B_ + b) * N_ + n] = acc;
}

__global__ __launch_bounds__(256) void ct_reduce_kernel(float* __restrict__ out)
{
    const int i = blockIdx.x * 256 + threadIdx.x;
    float s = 0.f;
    #pragma unroll
    for (int z = 0; z < 8; z++) s += g_ct[(size_t)z * B_ * N_ + i];
    out[i] = s;
}

// ===========================================================================
extern "C" void kernel_launch(void* const* d_in, const int* in_sizes, int n_in,
                              void* d_out, int out_size)
{
    const float* s_t_hat = (const float*)d_in[0];
    const float* h       = (const float*)d_in[1];
    const float* mask    = (const float*)d_in[2];
    const float* cov     = (const float*)d_in[3];
    const float* q_h     = (const float*)d_in[4];
    const float* Wh      = (const float*)d_in[5];
    const float* Wq      = (const float*)d_in[6];
    const float* Wc      = (const float*)d_in[7];
    const float* Wd      = (const float*)d_in[8];
    const float* bd      = (const float*)d_in[9];
    const float* vw      = (const float*)d_in[10];
    float* out = (float*)d_out;

    static bool attr_set = false;
    if (!attr_set) {
        cudaFuncSetAttribute(scores_mma, cudaFuncAttributeMaxDynamicSharedMemorySize, SMEM_TOTAL);
        attr_set = true;
    }

    conv_a_kernel<<<16384, 256>>>(h, q_h);
    conv_b_kernel<<<2048, 256>>>(Wh, Wq);
    dec_kernel<<<dim3(32, 128), 256>>>(s_t_hat, Wd, bd);
    scores_mma<<<dim3(NPART, M_ / 128), 256, SMEM_TOTAL>>>(Wc, vw, cov);
    softmax_kernel<<<32, 256>>>(mask, cov, out);
    ct_part_kernel<<<dim3(32, N_ / 256, 8), 256>>>(h, out);
    ct_reduce_kernel<<<B_ * N_ / 256, 256>>>(out);
}

// round 16
// speedup vs baseline: 2.4116x; 1.0835x over previous
#include <cuda_runtime.h>
#include <cuda_fp16.h>
#include <math.h>
#include <stdint.h>

#define B_    32
#define TK_   2048
#define N_    1024
#define M_    (B_ * TK_)        // 65536
#define KTOT  2048
#define NPART 4                 // N_/256 column blocks -> score partials

// ---------------- scratch (no allocs allowed) ----------------
__device__ float g_dec[B_ * N_];
__device__ float g_part[NPART * M_];
__device__ float g_ct[8 * B_ * N_];
// pre-converted fp16 operands: A = [h|q], B = [Wh|Wq], K-fused layout
__device__ __half g_A[(size_t)M_ * KTOT];
__device__ __half g_B[(size_t)N_ * KTOT];

// ---------------- smem layout (dynamic) ----------------
// K=64 per stage; fp16 tiles, row stride 72 elements (144B):
// 144 mod 128 = 16 -> 8 consecutive rows hit distinct 16B banks (ldmatrix clean)
#define ROWSTRIDE 144
#define A_OFF  0
#define B_OFF  18432                        // 128 rows * 144
#define STAGE_BYTES 55296                   // (128 + 256) rows * 144
#define NSTAGE 3
#define EPI_DEC (NSTAGE * STAGE_BYTES)      // 165888
#define EPI_WC  (EPI_DEC + 1024)
#define EPI_VW  (EPI_WC + 1024)
#define EPI_COV (EPI_VW + 1024)
#define EPI_RED (EPI_COV + 512)             // 128*16 floats = 8192B
#define SMEM_TOTAL (EPI_RED + 8192)         // 177664

__device__ __forceinline__ uint32_t smem_u32(const void* p) {
    uint32_t a;
    asm("{ .reg .u64 t; cvta.to.shared.u64 t, %1; cvt.u32.u64 %0, t; }" : "=r"(a) : "l"(p));
    return a;
}

// pack two fp32 into one uint32 holding fp16x2 (lo = x, hi = y)
__device__ __forceinline__ uint32_t pack_h2(float x, float y) {
    uint32_t r;
    asm("cvt.rn.f16x2.f32 %0, %1, %2;" : "=r"(r) : "f"(y), "f"(x));
    return r;
}

#define LDSM_X4(r0, r1, r2, r3, addr) \
    asm volatile("ldmatrix.sync.aligned.m8n8.x4.shared.b16 {%0,%1,%2,%3}, [%4];" \
                 : "=r"(r0), "=r"(r1), "=r"(r2), "=r"(r3) : "r"(addr))
#define MMA16816F16(d, a, b) \
    asm volatile("mma.sync.aligned.m16n8k16.row.col.f32.f16.f16.f32 " \
                 "{%0,%1,%2,%3}, {%4,%5,%6,%7}, {%8,%9}, {%0,%1,%2,%3};" \
                 : "+f"((d)[0]), "+f"((d)[1]), "+f"((d)[2]), "+f"((d)[3]) \
                 : "r"((a)[0]), "r"((a)[1]), "r"((a)[2]), "r"((a)[3]), \
                   "r"((b)[0]), "r"((b)[1]))
#define CP16(smaddr, gptr) \
    asm volatile("cp.async.cg.shared.global [%0], [%1], 16;" \
                 :: "r"(smaddr), "l"(gptr) : "memory")
#define CP_COMMIT() asm volatile("cp.async.commit_group;" ::: "memory")
#define CP_WAIT1()  asm volatile("cp.async.wait_group 1;" ::: "memory")

// ===========================================================================
// pre-conversion kernels (plain fp32 -> fp16)
// ===========================================================================
__global__ __launch_bounds__(256) void conv_a_kernel(
    const float* __restrict__ h, const float* __restrict__ q)
{
    const size_t UN = (size_t)M_ * (N_ / 4);
    const size_t total = 2 * UN;
    for (size_t u = (size_t)blockIdx.x * 256 + threadIdx.x; u < total;
         u += (size_t)gridDim.x * 256) {
        const int t = (u >= UN) ? 1 : 0;
        const size_t v = u - (t ? UN : 0);
        const size_t m = v >> 8;
        const int seg = (int)(v & 255);
        float4 val = *(const float4*)((t ? q : h) + m * N_ + seg * 4);
        size_t d = m * (size_t)KTOT + (size_t)t * N_ + (size_t)seg * 4;
        *(uint2*)(g_A + d) = make_uint2(pack_h2(val.x, val.y), pack_h2(val.z, val.w));
    }
}

__global__ __launch_bounds__(256) void conv_b_kernel(
    const float* __restrict__ Wh, const float* __restrict__ Wq)
{
    const size_t UN = (size_t)N_ * (N_ / 4);
    const size_t total = 2 * UN;
    for (size_t u = (size_t)blockIdx.x * 256 + threadIdx.x; u < total;
         u += (size_t)gridDim.x * 256) {
        const int t = (u >= UN) ? 1 : 0;
        const size_t v = u - (t ? UN : 0);
        const size_t n = v >> 8;
        const int seg = (int)(v & 255);
        float4 val = *(const float4*)((t ? Wq : Wh) + n * N_ + seg * 4);
        size_t d = n * (size_t)KTOT + (size_t)t * N_ + (size_t)seg * 4;
        *(uint2*)(g_B + d) = make_uint2(pack_h2(val.x, val.y), pack_h2(val.z, val.w));
    }
}

// ===========================================================================
// dec_feat[b][m] = s_t_hat[b] . W_d[m] + b_d[m]
// ===========================================================================
__global__ __launch_bounds__(256) void dec_kernel(
    const float* __restrict__ s_t_hat,
    const float* __restrict__ Wd,
    const float* __restrict__ bd)
{
    int b    = blockIdx.x;
    int warp = threadIdx.x >> 5;
    int lane = threadIdx.x & 31;
    int m    = blockIdx.y * 8 + warp;

    const float* sp = s_t_hat + (size_t)b * N_;
    const float* wp = Wd + (size_t)m * N_;
    float acc = 0.f;
    #pragma unroll 4
    for (int k = lane; k < N_; k += 32) acc = fmaf(sp[k], wp[k], acc);
    #pragma unroll
    for (int o = 16; o > 0; o >>= 1) acc += __shfl_xor_sync(0xffffffffu, acc, o);
    if (lane == 0) g_dec[(size_t)b * N_ + m] = acc + bd[m];
}

// ===========================================================================
// scores via plain fp16 mma.sync (fp32 accum).
// Block tile 128x256, 256 threads (8 warps, 2m x 4n, 64x64 per warp).
// K=64 per stage, NSTAGE=3 cp.async pipeline. grid (4, 512).
// ===========================================================================
__global__ __launch_bounds__(256, 1) void scores_mma(
    const float* __restrict__ Wc, const float* __restrict__ vw,
    const float* __restrict__ cov)
{
    extern __shared__ char sm[];
    const uint32_t smem = smem_u32(sm);
    const int tid  = threadIdx.x;
    const int lane = tid & 31;
    const int wid  = tid >> 5;
    const int wm   = wid & 1;       // 2 m-groups of 64
    const int wn   = wid >> 1;      // 4 n-groups of 64
    const int mBase = blockIdx.y * 128;
    const int nBase = blockIdx.x * 256;
    const int b     = mBase >> 11;
    const int trow  = mBase & (TK_ - 1);

    float* dec_s = (float*)(sm + EPI_DEC);
    float* wc_s  = (float*)(sm + EPI_WC);
    float* vw_s  = (float*)(sm + EPI_VW);
    float* cov_s = (float*)(sm + EPI_COV);
    float* red   = (float*)(sm + EPI_RED);

    dec_s[tid] = g_dec[(size_t)b * N_ + nBase + tid];
    wc_s[tid]  = Wc[nBase + tid];
    vw_s[tid]  = vw[nBase + tid];
    if (tid < 128) cov_s[tid] = cov[(size_t)b * TK_ + trow + tid];

    // ldmatrix lane-address components
    const int g = lane >> 3;
    const uint32_t a_row = (uint32_t)(((g & 1) << 3) + (lane & 7));
    const uint32_t a_col = (uint32_t)((g >> 1) << 3);
    const uint32_t b4_n  = (uint32_t)((lane >> 4) << 3);        // 0 or 8
    const uint32_t b4_k  = (uint32_t)(((lane >> 3) & 1) << 3);  // 0 or 8
    const uint32_t b4_r  = (uint32_t)(lane & 7);

    // cp.async: crow = tid>>3 (0..31), cseg = tid&7
    const int crow = tid >> 3, cseg = tid & 7;

    float acc[4][8][4];
    #pragma unroll
    for (int mf = 0; mf < 4; mf++)
        #pragma unroll
        for (int nf = 0; nf < 8; nf++)
            #pragma unroll
            for (int x = 0; x < 4; x++) acc[mf][nf][x] = 0.f;

    auto cp_stage = [&](int ks, int st) {
        const uint32_t sbase = smem + st * STAGE_BYTES;
        const int k0 = ks * 64;
        #pragma unroll
        for (int j = 0; j < 4; j++) {       // A: 128 rows
            const int row = crow + j * 32;
            const uint32_t soff = (uint32_t)(row * ROWSTRIDE + cseg * 16);
            const size_t ga = (size_t)(mBase + row) * KTOT + k0 + cseg * 8;
            CP16(sbase + A_OFF + soff, g_A + ga);
        }
        #pragma unroll
        for (int j = 0; j < 8; j++) {       // B: 256 rows
            const int row = crow + j * 32;
            const uint32_t soff = (uint32_t)(row * ROWSTRIDE + cseg * 16);
            const size_t gb = (size_t)(nBase + row) * KTOT + k0 + cseg * 8;
            CP16(sbase + B_OFF + soff, g_B + gb);
        }
    };

    auto mma_step = [&](int st) {
        const uint32_t Ab = smem + st * STAGE_BYTES + A_OFF;
        const uint32_t Bb = smem + st * STAGE_BYTES + B_OFF;
        #pragma unroll
        for (int kf = 0; kf < 4; kf++) {
            uint32_t ah[4][4], bh[8][2];
            #pragma unroll
            for (int mf = 0; mf < 4; mf++) {
                uint32_t off = (uint32_t)((wm * 64 + mf * 16 + a_row) * ROWSTRIDE
                                          + (kf * 16 + a_col) * 2);
                LDSM_X4(ah[mf][0], ah[mf][1], ah[mf][2], ah[mf][3], Ab + off);
            }
            #pragma unroll
            for (int np = 0; np < 4; np++) {
                uint32_t off = (uint32_t)((wn * 64 + np * 16 + b4_n + b4_r) * ROWSTRIDE
                                          + (kf * 16 + b4_k) * 2);
                LDSM_X4(bh[np*2][0], bh[np*2][1], bh[np*2+1][0], bh[np*2+1][1], Bb + off);
            }
            #pragma unroll
            for (int mf = 0; mf < 4; mf++)
                #pragma unroll
                for (int nf = 0; nf < 8; nf++)
                    MMA16816F16(acc[mf][nf], ah[mf], bh[nf]);
        }
    };

    // prologue: fill NSTAGE-1 = 2 stages
    cp_stage(0, 0); CP_COMMIT();
    cp_stage(1, 1); CP_COMMIT();

    const int NKS = KTOT / 64;   // 32
    int cur = 0, nxt = 2;        // stage indices mod 3
    for (int ks = 0; ks < NKS; ks++) {
        CP_WAIT1();
        __syncthreads();
        const int pf = ks + 2;
        if (pf < NKS) cp_stage(pf, nxt);
        CP_COMMIT();
        mma_step(cur);
        cur = (cur == 2) ? 0 : cur + 1;
        nxt = (nxt == 2) ? 0 : nxt + 1;
    }

    // fused epilogue: tanh + dot with v_w, per-row partials
    #pragma unroll
    for (int mf = 0; mf < 4; mf++) {
        const int rA = wm * 64 + mf * 16 + (lane >> 2);
        const int rB = rA + 8;
        const float covA = cov_s[rA];
        const float covB = cov_s[rB];
        float sA = 0.f, sB = 0.f;
        #pragma unroll
        for (int nf = 0; nf < 8; nf++) {
            const int n0 = wn * 64 + nf * 8 + ((lane & 3) << 1);
            const float d0 = dec_s[n0],   d1 = dec_s[n0 + 1];
            const float w0 = wc_s[n0],    w1 = wc_s[n0 + 1];
            const float v0 = vw_s[n0],    v1 = vw_s[n0 + 1];
            sA += tanhf(acc[mf][nf][0] + d0 + covA * w0) * v0
                + tanhf(acc[mf][nf][1] + d1 + covA * w1) * v1;
            sB += tanhf(acc[mf][nf][2] + d0 + covB * w0) * v0
                + tanhf(acc[mf][nf][3] + d1 + covB * w1) * v1;
        }
        const int colslot = wn * 4 + (lane & 3);
        red[rA * 16 + colslot] = sA;
        red[rB * 16 + colslot] = sB;
    }
    __syncthreads();
    if (tid < 128) {
        float s = 0.f;
        #pragma unroll
        for (int x = 0; x < 16; x++) s += red[tid * 16 + x];
        g_part[(size_t)blockIdx.x * M_ + mBase + tid] = s;
    }
}

// ===========================================================================
// softmax with mask + renormalize; writes attn and coverage_out
// ===========================================================================
__global__ __launch_bounds__(256) void softmax_kernel(
    const float* __restrict__ mask,
    const float* __restrict__ cov,
    float* __restrict__ out)
{
    __shared__ float sh[TK_];
    __shared__ float red[256];
    const int b = blockIdx.x, tid = threadIdx.x;

    float lmax = -1e30f;
    for (int t = tid; t < TK_; t += 256) {
        float s = 0.f;
        #pragma unroll
        for (int c = 0; c < NPART; c++) s += g_part[(size_t)c * M_ + (size_t)b * TK_ + t];
        sh[t] = s;
        lmax = fmaxf(lmax, s);
    }
    red[tid] = lmax; __syncthreads();
    for (int o = 128; o > 0; o >>= 1) {
        if (tid < o) red[tid] = fmaxf(red[tid], red[tid + o]);
        __syncthreads();
    }
    const float mx = red[0];
    __syncthreads();

    float lsum = 0.f;
    for (int t = tid; t < TK_; t += 256) {
        float e = expf(sh[t] - mx) * mask[(size_t)b * TK_ + t];
        sh[t] = e;
        lsum += e;
    }
    red[tid] = lsum; __syncthreads();
    for (int o = 128; o > 0; o >>= 1) {
        if (tid < o) red[tid] += red[tid + o];
        __syncthreads();
    }
    const float inv = 1.f / red[0];

    for (int t = tid; t < TK_; t += 256) {
        float a = sh[t] * inv;
        out[(size_t)B_ * N_ + (size_t)b * TK_ + t] = a;
        out[(size_t)B_ * N_ + (size_t)B_ * TK_ + (size_t)b * TK_ + t] =
            cov[(size_t)b * TK_ + t] + a;
    }
}

// ===========================================================================
// c_t partials over 8 T-chunks, then reduce
// ===========================================================================
__global__ __launch_bounds__(256) void ct_part_kernel(
    const float* __restrict__ h,
    const float* __restrict__ out)
{
    __shared__ float ash[256];
    const int b = blockIdx.x;
    const int n = blockIdx.y * 256 + threadIdx.x;
    const int z = blockIdx.z;
    const float* attn = out + (size_t)B_ * N_ + (size_t)b * TK_ + z * 256;

    ash[threadIdx.x] = attn[threadIdx.x];
    __syncthreads();
    const float* hp = h + ((size_t)b * TK_ + z * 256) * N_ + n;
    float acc = 0.f;
    #pragma unroll 8
    for (int tt = 0; tt < 256; tt++)
        acc = fmaf(ash[tt], hp[(size_t)tt * N_], acc);
    g_ct[((size_t)z * B_ + b) * N_ + n] = acc;
}

__global__ __launch_bounds__(256) void ct_reduce_kernel(float* __restrict__ out)
{
    const int i = blockIdx.x * 256 + threadIdx.x;
    float s = 0.f;
    #pragma unroll
    for (int z = 0; z < 8; z++) s += g_ct[(size_t)z * B_ * N_ + i];
    out[i] = s;
}

// ===========================================================================
extern "C" void kernel_launch(void* const* d_in, const int* in_sizes, int n_in,
                              void* d_out, int out_size)
{
    const float* s_t_hat = (const float*)d_in[0];
    const float* h       = (const float*)d_in[1];
    const float* mask    = (const float*)d_in[2];
    const float* cov     = (const float*)d_in[3];
    const float* q_h     = (const float*)d_in[4];
    const float* Wh      = (const float*)d_in[5];
    const float* Wq      = (const float*)d_in[6];
    const float* Wc      = (const float*)d_in[7];
    const float* Wd      = (const float*)d_in[8];
    const float* bd      = (const float*)d_in[9];
    const float* vw      = (const float*)d_in[10];
    float* out = (float*)d_out;

    static bool attr_set = false;
    if (!attr_set) {
        cudaFuncSetAttribute(scores_mma, cudaFuncAttributeMaxDynamicSharedMemorySize, SMEM_TOTAL);
        attr_set = true;
    }

    conv_a_kernel<<<16384, 256>>>(h, q_h);
    conv_b_kernel<<<2048, 256>>>(Wh, Wq);
    dec_kernel<<<dim3(32, 128), 256>>>(s_t_hat, Wd, bd);
    scores_mma<<<dim3(NPART, M_ / 128), 256, SMEM_TOTAL>>>(Wc, vw, cov);
    softmax_kernel<<<32, 256>>>(mask, cov, out);
    ct_part_kernel<<<dim3(32, N_ / 256, 8), 256>>>(h, out);
    ct_reduce_kernel<<<B_ * N_ / 256, 256>>>(out);
}

// round 17
// speedup vs baseline: 2.4765x; 1.0269x over previous
#include <cuda_runtime.h>
#include <cuda_fp16.h>
#include <math.h>
#include <stdint.h>

#define B_    32
#define TK_   2048
#define N_    1024
#define M_    (B_ * TK_)        // 65536
#define KTOT  2048
#define NPART 4                 // N_/256 column blocks -> score partials

// ---------------- scratch (no allocs allowed) ----------------
__device__ float g_dec[B_ * N_];
__device__ float g_part[NPART * M_];
__device__ float g_ct[8 * B_ * N_];
// pre-converted fp16 operands: A = [h|q], B = [Wh|Wq], K-fused layout
__device__ __half g_A[(size_t)M_ * KTOT];
__device__ __half g_B[(size_t)N_ * KTOT];

// ---------------- smem layout (dynamic) ----------------
// K=128 per stage; fp16 tiles, row stride 136 elements (272B):
// 272 mod 128 = 16 -> 8 consecutive rows hit distinct 16B banks (ldmatrix clean)
#define ROWSTRIDE 272
#define A_OFF  0
#define B_OFF  34816                        // 128 rows * 272
#define STAGE_BYTES 104448                  // (128 + 256) rows * 272
#define NSTAGE 2
#define EPI_DEC (NSTAGE * STAGE_BYTES)      // 208896
#define EPI_WC  (EPI_DEC + 1024)
#define EPI_VW  (EPI_WC + 1024)
#define EPI_COV (EPI_VW + 1024)
#define EPI_RED (EPI_COV + 512)             // 128*16 floats = 8192B
#define SMEM_TOTAL (EPI_RED + 8192)         // 220672

__device__ __forceinline__ uint32_t smem_u32(const void* p) {
    uint32_t a;
    asm("{ .reg .u64 t; cvta.to.shared.u64 t, %1; cvt.u32.u64 %0, t; }" : "=r"(a) : "l"(p));
    return a;
}

// pack two fp32 into one uint32 holding fp16x2 (lo = x, hi = y)
__device__ __forceinline__ uint32_t pack_h2(float x, float y) {
    uint32_t r;
    asm("cvt.rn.f16x2.f32 %0, %1, %2;" : "=r"(r) : "f"(y), "f"(x));
    return r;
}

#define LDSM_X4(r0, r1, r2, r3, addr) \
    asm volatile("ldmatrix.sync.aligned.m8n8.x4.shared.b16 {%0,%1,%2,%3}, [%4];" \
                 : "=r"(r0), "=r"(r1), "=r"(r2), "=r"(r3) : "r"(addr))
#define MMA16816F16(d, a, b) \
    asm volatile("mma.sync.aligned.m16n8k16.row.col.f32.f16.f16.f32 " \
                 "{%0,%1,%2,%3}, {%4,%5,%6,%7}, {%8,%9}, {%0,%1,%2,%3};" \
                 : "+f"((d)[0]), "+f"((d)[1]), "+f"((d)[2]), "+f"((d)[3]) \
                 : "r"((a)[0]), "r"((a)[1]), "r"((a)[2]), "r"((a)[3]), \
                   "r"((b)[0]), "r"((b)[1]))
#define CP16(smaddr, gptr) \
    asm volatile("cp.async.cg.shared.global [%0], [%1], 16;" \
                 :: "r"(smaddr), "l"(gptr) : "memory")
#define CP_COMMIT() asm volatile("cp.async.commit_group;" ::: "memory")
#define CP_WAIT0()  asm volatile("cp.async.wait_group 0;" ::: "memory")

// ===========================================================================
// pre-conversion kernels (plain fp32 -> fp16)
// ===========================================================================
__global__ __launch_bounds__(256) void conv_a_kernel(
    const float* __restrict__ h, const float* __restrict__ q)
{
    const size_t UN = (size_t)M_ * (N_ / 4);
    const size_t total = 2 * UN;
    for (size_t u = (size_t)blockIdx.x * 256 + threadIdx.x; u < total;
         u += (size_t)gridDim.x * 256) {
        const int t = (u >= UN) ? 1 : 0;
        const size_t v = u - (t ? UN : 0);
        const size_t m = v >> 8;
        const int seg = (int)(v & 255);
        float4 val = *(const float4*)((t ? q : h) + m * N_ + seg * 4);
        size_t d = m * (size_t)KTOT + (size_t)t * N_ + (size_t)seg * 4;
        *(uint2*)(g_A + d) = make_uint2(pack_h2(val.x, val.y), pack_h2(val.z, val.w));
    }
}

__global__ __launch_bounds__(256) void conv_b_kernel(
    const float* __restrict__ Wh, const float* __restrict__ Wq)
{
    const size_t UN = (size_t)N_ * (N_ / 4);
    const size_t total = 2 * UN;
    for (size_t u = (size_t)blockIdx.x * 256 + threadIdx.x; u < total;
         u += (size_t)gridDim.x * 256) {
        const int t = (u >= UN) ? 1 : 0;
        const size_t v = u - (t ? UN : 0);
        const size_t n = v >> 8;
        const int seg = (int)(v & 255);
        float4 val = *(const float4*)((t ? Wq : Wh) + n * N_ + seg * 4);
        size_t d = n * (size_t)KTOT + (size_t)t * N_ + (size_t)seg * 4;
        *(uint2*)(g_B + d) = make_uint2(pack_h2(val.x, val.y), pack_h2(val.z, val.w));
    }
}

// ===========================================================================
// dec_feat[b][m] = s_t_hat[b] . W_d[m] + b_d[m]
// ===========================================================================
__global__ __launch_bounds__(256) void dec_kernel(
    const float* __restrict__ s_t_hat,
    const float* __restrict__ Wd,
    const float* __restrict__ bd)
{
    int b    = blockIdx.x;
    int warp = threadIdx.x >> 5;
    int lane = threadIdx.x & 31;
    int m    = blockIdx.y * 8 + warp;

    const float* sp = s_t_hat + (size_t)b * N_;
    const float* wp = Wd + (size_t)m * N_;
    float acc = 0.f;
    #pragma unroll 4
    for (int k = lane; k < N_; k += 32) acc = fmaf(sp[k], wp[k], acc);
    #pragma unroll
    for (int o = 16; o > 0; o >>= 1) acc += __shfl_xor_sync(0xffffffffu, acc, o);
    if (lane == 0) g_dec[(size_t)b * N_ + m] = acc + bd[m];
}

// ===========================================================================
// scores via plain fp16 mma.sync (fp32 accum).
// Block tile 128x256, 256 threads (8 warps, 2m x 4n, 64x64 per warp).
// K=128 per stage, NSTAGE=2 cp.async pipeline, 16 mainloop iterations.
// grid (4, 512).
// ===========================================================================
__global__ __launch_bounds__(256, 1) void scores_mma(
    const float* __restrict__ Wc, const float* __restrict__ vw,
    const float* __restrict__ cov)
{
    extern __shared__ char sm[];
    const uint32_t smem = smem_u32(sm);
    const int tid  = threadIdx.x;
    const int lane = tid & 31;
    const int wid  = tid >> 5;
    const int wm   = wid & 1;       // 2 m-groups of 64
    const int wn   = wid >> 1;      // 4 n-groups of 64
    const int mBase = blockIdx.y * 128;
    const int nBase = blockIdx.x * 256;
    const int b     = mBase >> 11;
    const int trow  = mBase & (TK_ - 1);

    float* dec_s = (float*)(sm + EPI_DEC);
    float* wc_s  = (float*)(sm + EPI_WC);
    float* vw_s  = (float*)(sm + EPI_VW);
    float* cov_s = (float*)(sm + EPI_COV);
    float* red   = (float*)(sm + EPI_RED);

    dec_s[tid] = g_dec[(size_t)b * N_ + nBase + tid];
    wc_s[tid]  = Wc[nBase + tid];
    vw_s[tid]  = vw[nBase + tid];
    if (tid < 128) cov_s[tid] = cov[(size_t)b * TK_ + trow + tid];

    // ldmatrix lane-address components
    const int g = lane >> 3;
    const uint32_t a_row = (uint32_t)(((g & 1) << 3) + (lane & 7));
    const uint32_t a_col = (uint32_t)((g >> 1) << 3);
    const uint32_t b4_n  = (uint32_t)((lane >> 4) << 3);        // 0 or 8
    const uint32_t b4_k  = (uint32_t)(((lane >> 3) & 1) << 3);  // 0 or 8
    const uint32_t b4_r  = (uint32_t)(lane & 7);

    // cp.async: 16 threads cover one 256B row; crow16 = tid>>4, cseg16 = tid&15
    const int crow16 = tid >> 4, cseg16 = tid & 15;

    float acc[4][8][4];
    #pragma unroll
    for (int mf = 0; mf < 4; mf++)
        #pragma unroll
        for (int nf = 0; nf < 8; nf++)
            #pragma unroll
            for (int x = 0; x < 4; x++) acc[mf][nf][x] = 0.f;

    auto cp_stage = [&](int ks, int st) {
        const uint32_t sbase = smem + st * STAGE_BYTES;
        const int k0 = ks * 128;
        #pragma unroll
        for (int j = 0; j < 8; j++) {       // A: 128 rows
            const int row = crow16 + j * 16;
            const uint32_t soff = (uint32_t)(row * ROWSTRIDE + cseg16 * 16);
            const size_t ga = (size_t)(mBase + row) * KTOT + k0 + cseg16 * 8;
            CP16(sbase + A_OFF + soff, g_A + ga);
        }
        #pragma unroll
        for (int j = 0; j < 16; j++) {      // B: 256 rows
            const int row = crow16 + j * 16;
            const uint32_t soff = (uint32_t)(row * ROWSTRIDE + cseg16 * 16);
            const size_t gb = (size_t)(nBase + row) * KTOT + k0 + cseg16 * 8;
            CP16(sbase + B_OFF + soff, g_B + gb);
        }
    };

    auto mma_step = [&](int st) {
        const uint32_t Ab = smem + st * STAGE_BYTES + A_OFF;
        const uint32_t Bb = smem + st * STAGE_BYTES + B_OFF;
        #pragma unroll
        for (int kf = 0; kf < 8; kf++) {
            uint32_t ah[4][4], bh[8][2];
            #pragma unroll
            for (int mf = 0; mf < 4; mf++) {
                uint32_t off = (uint32_t)((wm * 64 + mf * 16 + a_row) * ROWSTRIDE
                                          + (kf * 16 + a_col) * 2);
                LDSM_X4(ah[mf][0], ah[mf][1], ah[mf][2], ah[mf][3], Ab + off);
            }
            #pragma unroll
            for (int np = 0; np < 4; np++) {
                uint32_t off = (uint32_t)((wn * 64 + np * 16 + b4_n + b4_r) * ROWSTRIDE
                                          + (kf * 16 + b4_k) * 2);
                LDSM_X4(bh[np*2][0], bh[np*2][1], bh[np*2+1][0], bh[np*2+1][1], Bb + off);
            }
            #pragma unroll
            for (int mf = 0; mf < 4; mf++)
                #pragma unroll
                for (int nf = 0; nf < 8; nf++)
                    MMA16816F16(acc[mf][nf], ah[mf], bh[nf]);
        }
    };

    // prologue: fill stage 0
    cp_stage(0, 0); CP_COMMIT();

    const int NKS = KTOT / 128;   // 16
    for (int ks = 0; ks < NKS; ks++) {
        CP_WAIT0();
        __syncthreads();
        if (ks + 1 < NKS) cp_stage(ks + 1, (ks + 1) & 1);
        CP_COMMIT();
        mma_step(ks & 1);
    }

    // fused epilogue: tanh + dot with v_w, per-row partials
    #pragma unroll
    for (int mf = 0; mf < 4; mf++) {
        const int rA = wm * 64 + mf * 16 + (lane >> 2);
        const int rB = rA + 8;
        const float covA = cov_s[rA];
        const float covB = cov_s[rB];
        float sA = 0.f, sB = 0.f;
        #pragma unroll
        for (int nf = 0; nf < 8; nf++) {
            const int n0 = wn * 64 + nf * 8 + ((lane & 3) << 1);
            const float d0 = dec_s[n0],   d1 = dec_s[n0 + 1];
            const float w0 = wc_s[n0],    w1 = wc_s[n0 + 1];
            const float v0 = vw_s[n0],    v1 = vw_s[n0 + 1];
            sA += tanhf(acc[mf][nf][0] + d0 + covA * w0) * v0
                + tanhf(acc[mf][nf][1] + d1 + covA * w1) * v1;
            sB += tanhf(acc[mf][nf][2] + d0 + covB * w0) * v0
                + tanhf(acc[mf][nf][3] + d1 + covB * w1) * v1;
        }
        const int colslot = wn * 4 + (lane & 3);
        red[rA * 16 + colslot] = sA;
        red[rB * 16 + colslot] = sB;
    }
    __syncthreads();
    if (tid < 128) {
        float s = 0.f;
        #pragma unroll
        for (int x = 0; x < 16; x++) s += red[tid * 16 + x];
        g_part[(size_t)blockIdx.x * M_ + mBase + tid] = s;
    }
}

// ===========================================================================
// softmax with mask + renormalize; writes attn and coverage_out
// ===========================================================================
__global__ __launch_bounds__(256) void softmax_kernel(
    const float* __restrict__ mask,
    const float* __restrict__ cov,
    float* __restrict__ out)
{
    __shared__ float sh[TK_];
    __shared__ float red[256];
    const int b = blockIdx.x, tid = threadIdx.x;

    float lmax = -1e30f;
    for (int t = tid; t < TK_; t += 256) {
        float s = 0.f;
        #pragma unroll
        for (int c = 0; c < NPART; c++) s += g_part[(size_t)c * M_ + (size_t)b * TK_ + t];
        sh[t] = s;
        lmax = fmaxf(lmax, s);
    }
    red[tid] = lmax; __syncthreads();
    for (int o = 128; o > 0; o >>= 1) {
        if (tid < o) red[tid] = fmaxf(red[tid], red[tid + o]);
        __syncthreads();
    }
    const float mx = red[0];
    __syncthreads();

    float lsum = 0.f;
    for (int t = tid; t < TK_; t += 256) {
        float e = expf(sh[t] - mx) * mask[(size_t)b * TK_ + t];
        sh[t] = e;
        lsum += e;
    }
    red[tid] = lsum; __syncthreads();
    for (int o = 128; o > 0; o >>= 1) {
        if (tid < o) red[tid] += red[tid + o];
        __syncthreads();
    }
    const float inv = 1.f / red[0];

    for (int t = tid; t < TK_; t += 256) {
        float a = sh[t] * inv;
        out[(size_t)B_ * N_ + (size_t)b * TK_ + t] = a;
        out[(size_t)B_ * N_ + (size_t)B_ * TK_ + (size_t)b * TK_ + t] =
            cov[(size_t)b * TK_ + t] + a;
    }
}

// ===========================================================================
// c_t partials over 8 T-chunks, then reduce
// ===========================================================================
__global__ __launch_bounds__(256) void ct_part_kernel(
    const float* __restrict__ h,
    const float* __restrict__ out)
{
    __shared__ float ash[256];
    const int b = blockIdx.x;
    const int n = blockIdx.y * 256 + threadIdx.x;
    const int z = blockIdx.z;
    const float* attn = out + (size_t)B_ * N_ + (size_t)b * TK_ + z * 256;

    ash[threadIdx.x] = attn[threadIdx.x];
    __syncthreads();
    const float* hp = h + ((size_t)b * TK_ + z * 256) * N_ + n;
    float acc = 0.f;
    #pragma unroll 8
    for (int tt = 0; tt < 256; tt++)
        acc = fmaf(ash[tt], hp[(size_t)tt * N_], acc);
    g_ct[((size_t)z * B_ + b) * N_ + n] = acc;
}

__global__ __launch_bounds__(256) void ct_reduce_kernel(float* __restrict__ out)
{
    const int i = blockIdx.x * 256 + threadIdx.x;
    float s = 0.f;
    #pragma unroll
    for (int z = 0; z < 8; z++) s += g_ct[(size_t)z * B_ * N_ + i];
    out[i] = s;
}

// ===========================================================================
extern "C" void kernel_launch(void* const* d_in, const int* in_sizes, int n_in,
                              void* d_out, int out_size)
{
    const float* s_t_hat = (const float*)d_in[0];
    const float* h       = (const float*)d_in[1];
    const float* mask    = (const float*)d_in[2];
    const float* cov     = (const float*)d_in[3];
    const float* q_h     = (const float*)d_in[4];
    const float* Wh      = (const float*)d_in[5];
    const float* Wq      = (const float*)d_in[6];
    const float* Wc      = (const float*)d_in[7];
    const float* Wd      = (const float*)d_in[8];
    const float* bd      = (const float*)d_in[9];
    const float* vw      = (const float*)d_in[10];
    float* out = (float*)d_out;

    static bool attr_set = false;
    if (!attr_set) {
        cudaFuncSetAttribute(scores_mma, cudaFuncAttributeMaxDynamicSharedMemorySize, SMEM_TOTAL);
        attr_set = true;
    }

    conv_a_kernel<<<16384, 256>>>(h, q_h);
    conv_b_kernel<<<2048, 256>>>(Wh, Wq);
    dec_kernel<<<dim3(32, 128), 256>>>(s_t_hat, Wd, bd);
    scores_mma<<<dim3(NPART, M_ / 128), 256, SMEM_TOTAL>>>(Wc, vw, cov);
    softmax_kernel<<<32, 256>>>(mask, cov, out);
    ct_part_kernel<<<dim3(32, N_ / 256, 8), 256>>>(h, out);
    ct_reduce_kernel<<<B_ * N_ / 256, 256>>>(out);
}